// round 1
// baseline (speedup 1.0000x reference)
#include <cuda_runtime.h>
#include <math.h>

// Problem dims
#define S_  2048
#define B_  2
#define D_  1024
#define H_  16
#define DK_ 64
#define E_  8
#define F_  4096
#define T_  (S_*B_)          // 4096 tokens
#define OUT_TOTAL (T_*D_ + E_ + E_ + 1 + T_)   // out | counts | rps | n_dropped | pmax

// -------- scratch (device globals; allocation-free) --------
__device__ float g_z1[T_*D_];
__device__ float g_q [T_*D_];
__device__ float g_k [T_*D_];
__device__ float g_v [T_*D_];
__device__ float g_o [T_*D_];
__device__ float g_x2[T_*D_];
__device__ float g_z2[T_*D_];
__device__ float g_probs[T_*E_];
__device__ float g_pmax[T_];
__device__ int   g_route[T_];
__device__ int   g_etok[E_*T_];
__device__ int   g_ecount[E_];
__device__ float g_h[(size_t)T_*F_];

// ---------------- init ----------------
__global__ void init_kernel() {
    int i = threadIdx.x;
    if (i < E_) g_ecount[i] = 0;
}

// ---------------- LayerNorm ----------------
__global__ void ln_kernel(const float* __restrict__ x,
                          const float* __restrict__ gam,
                          const float* __restrict__ bet,
                          float* __restrict__ z) {
    int t = blockIdx.x;
    const float* row = x + (size_t)t * D_;
    __shared__ float red[256];
    __shared__ float stats[2];
    float s = 0.f, sq = 0.f;
    for (int i = threadIdx.x; i < D_; i += 256) {
        float v = row[i];
        s += v; sq += v * v;
    }
    red[threadIdx.x] = s; __syncthreads();
    for (int o = 128; o; o >>= 1) { if (threadIdx.x < o) red[threadIdx.x] += red[threadIdx.x+o]; __syncthreads(); }
    if (threadIdx.x == 0) stats[0] = red[0];
    __syncthreads();
    red[threadIdx.x] = sq; __syncthreads();
    for (int o = 128; o; o >>= 1) { if (threadIdx.x < o) red[threadIdx.x] += red[threadIdx.x+o]; __syncthreads(); }
    if (threadIdx.x == 0) stats[1] = red[0];
    __syncthreads();
    float mean = stats[0] * (1.f / D_);
    float var  = stats[1] * (1.f / D_) - mean * mean;
    float inv  = rsqrtf(var + 1e-5f);
    float* zr = z + (size_t)t * D_;
    for (int i = threadIdx.x; i < D_; i += 256)
        zr[i] = (row[i] - mean) * inv * gam[i] + bet[i];
}

// ---------------- generic tiled GEMM ----------------
// C[tok,n] = op( A[tok,:K] @ W[:K,n] + bias[n] ), BM=BN=64, BK=16, 256 threads, 4x4/thread.
// gather != null: rows gathered from expert token list (expert = blockIdx.z),
//                 W/bias offset by expert.
#define BM 64
#define BN 64
#define BK 16
__global__ void gemm_kernel(const float* __restrict__ A,
                            const float* __restrict__ W,
                            const float* __restrict__ bias,
                            const float* __restrict__ res,       // nullable
                            const float* __restrict__ rowscale,  // nullable
                            float* __restrict__ C,
                            int M, int N, int K,
                            const int* __restrict__ gather,      // nullable, [E_][T_]
                            const int* __restrict__ gcount,      // nullable, [E_]
                            int relu_flag) {
    int e  = blockIdx.z;
    int m0 = blockIdx.y * BM;
    int n0 = blockIdx.x * BN;
    const int* glist = nullptr;
    int mcnt = M;
    if (gather) {
        glist = gather + (size_t)e * T_;
        mcnt  = gcount[e];
        if (m0 >= mcnt) return;
        W    += (size_t)e * K * N;
        bias += (size_t)e * N;
    }
    __shared__ float As[BK][BM];
    __shared__ float Ws[BK][BN];
    int tid = threadIdx.x;
    int tx = tid & 15, ty = tid >> 4;
    int ar = tid >> 2, ak = (tid & 3) * 4;       // A load: row ar, 4 k's
    int wk = tid >> 4, wn = (tid & 15) * 4;      // W load: k row wk, 4 n's

    int arow = m0 + ar;
    int a_tok = arow;
    bool a_valid = true;
    if (gather) {
        if (arow < mcnt) a_tok = glist[arow];
        else { a_valid = false; a_tok = 0; }
    }
    const float* Aptr = A + (size_t)a_tok * K;
    float acc[4][4];
    #pragma unroll
    for (int i = 0; i < 4; i++)
        #pragma unroll
        for (int j = 0; j < 4; j++) acc[i][j] = 0.f;

    for (int k0 = 0; k0 < K; k0 += BK) {
        float4 av = a_valid ? *(const float4*)(Aptr + k0 + ak) : make_float4(0,0,0,0);
        As[ak+0][ar] = av.x; As[ak+1][ar] = av.y; As[ak+2][ar] = av.z; As[ak+3][ar] = av.w;
        float4 wv = *(const float4*)(W + (size_t)(k0 + wk) * N + n0 + wn);
        *(float4*)&Ws[wk][wn] = wv;
        __syncthreads();
        #pragma unroll
        for (int kk = 0; kk < BK; kk++) {
            float a0 = As[kk][ty*4+0], a1 = As[kk][ty*4+1],
                  a2 = As[kk][ty*4+2], a3 = As[kk][ty*4+3];
            float w0 = Ws[kk][tx*4+0], w1 = Ws[kk][tx*4+1],
                  w2 = Ws[kk][tx*4+2], w3 = Ws[kk][tx*4+3];
            acc[0][0] += a0*w0; acc[0][1] += a0*w1; acc[0][2] += a0*w2; acc[0][3] += a0*w3;
            acc[1][0] += a1*w0; acc[1][1] += a1*w1; acc[1][2] += a1*w2; acc[1][3] += a1*w3;
            acc[2][0] += a2*w0; acc[2][1] += a2*w1; acc[2][2] += a2*w2; acc[2][3] += a2*w3;
            acc[3][0] += a3*w0; acc[3][1] += a3*w1; acc[3][2] += a3*w2; acc[3][3] += a3*w3;
        }
        __syncthreads();
    }
    #pragma unroll
    for (int i = 0; i < 4; i++) {
        int m = ty * 4 + i;
        int row = m0 + m;
        if (gather && row >= mcnt) continue;
        int tok = gather ? glist[row] : row;
        float sc = rowscale ? rowscale[tok] : 1.f;
        #pragma unroll
        for (int j = 0; j < 4; j++) {
            int n = n0 + tx * 4 + j;
            float v = acc[i][j] + bias[n];
            if (relu_flag) v = fmaxf(v, 0.f);
            v *= sc;
            if (res) v += res[(size_t)tok * N + n];
            C[(size_t)tok * N + n] = v;
        }
    }
}

// ---------------- flash attention ----------------
// grid: (S/64, B*H). 256 threads, 4x4/thread. BM=BN=64, DK=64. No mask (all True).
__global__ void attn_kernel(const float* __restrict__ q,
                            const float* __restrict__ k,
                            const float* __restrict__ v,
                            float* __restrict__ o) {
    __shared__ float qT[DK_][64];   // [d][m]
    __shared__ float kT[DK_][64];   // [d][n]; reused as P[64][64] flat
    __shared__ float vS[64][DK_];   // [n][d]
    int bh = blockIdx.y;
    int b = bh % B_, h = bh / B_;
    int s0 = blockIdx.x * 64;
    int tid = threadIdx.x, tx = tid & 15, ty = tid >> 4;
    const float scale = 0.125f;   // 1/sqrt(64)

    for (int idx = tid; idx < 64 * DK_; idx += 256) {
        int m = idx >> 6, d = idx & 63;
        int t = (s0 + m) * B_ + b;
        qT[d][m] = q[(size_t)t * D_ + h * DK_ + d];
    }
    float acc[4][4], mrow[4], lrow[4];
    #pragma unroll
    for (int i = 0; i < 4; i++) {
        mrow[i] = -INFINITY; lrow[i] = 0.f;
        #pragma unroll
        for (int j = 0; j < 4; j++) acc[i][j] = 0.f;
    }
    __syncthreads();

    for (int n0 = 0; n0 < S_; n0 += 64) {
        for (int idx = tid; idx < 64 * DK_; idx += 256) {
            int n = idx >> 6, d = idx & 63;
            int t = (n0 + n) * B_ + b;
            kT[d][n] = k[(size_t)t * D_ + h * DK_ + d];
            vS[n][d] = v[(size_t)t * D_ + h * DK_ + d];
        }
        __syncthreads();
        float s[4][4];
        #pragma unroll
        for (int i = 0; i < 4; i++)
            #pragma unroll
            for (int j = 0; j < 4; j++) s[i][j] = 0.f;
        for (int d = 0; d < DK_; d++) {
            float a0 = qT[d][ty*4+0], a1 = qT[d][ty*4+1],
                  a2 = qT[d][ty*4+2], a3 = qT[d][ty*4+3];
            float w0 = kT[d][tx*4+0], w1 = kT[d][tx*4+1],
                  w2 = kT[d][tx*4+2], w3 = kT[d][tx*4+3];
            s[0][0] += a0*w0; s[0][1] += a0*w1; s[0][2] += a0*w2; s[0][3] += a0*w3;
            s[1][0] += a1*w0; s[1][1] += a1*w1; s[1][2] += a1*w2; s[1][3] += a1*w3;
            s[2][0] += a2*w0; s[2][1] += a2*w1; s[2][2] += a2*w2; s[2][3] += a2*w3;
            s[3][0] += a3*w0; s[3][1] += a3*w1; s[3][2] += a3*w2; s[3][3] += a3*w3;
        }
        float p[4][4], alpha[4];
        #pragma unroll
        for (int i = 0; i < 4; i++) {
            float mx = -INFINITY;
            #pragma unroll
            for (int j = 0; j < 4; j++) { s[i][j] *= scale; mx = fmaxf(mx, s[i][j]); }
            #pragma unroll
            for (int off = 8; off; off >>= 1)
                mx = fmaxf(mx, __shfl_xor_sync(0xffffffffu, mx, off, 16));
            float newm = fmaxf(mrow[i], mx);
            float ps = 0.f;
            #pragma unroll
            for (int j = 0; j < 4; j++) { p[i][j] = expf(s[i][j] - newm); ps += p[i][j]; }
            #pragma unroll
            for (int off = 8; off; off >>= 1)
                ps += __shfl_xor_sync(0xffffffffu, ps, off, 16);
            alpha[i] = expf(mrow[i] - newm);
            lrow[i] = lrow[i] * alpha[i] + ps;
            mrow[i] = newm;
        }
        __syncthreads();   // everyone done reading kT as K
        float* pS = &kT[0][0];
        #pragma unroll
        for (int i = 0; i < 4; i++) {
            #pragma unroll
            for (int j = 0; j < 4; j++) {
                pS[(ty*4+i)*64 + tx*4+j] = p[i][j];
                acc[i][j] *= alpha[i];
            }
        }
        __syncthreads();
        for (int n = 0; n < 64; n++) {
            float p0 = pS[(ty*4+0)*64+n], p1 = pS[(ty*4+1)*64+n],
                  p2 = pS[(ty*4+2)*64+n], p3 = pS[(ty*4+3)*64+n];
            float v0 = vS[n][tx*4+0], v1 = vS[n][tx*4+1],
                  v2 = vS[n][tx*4+2], v3 = vS[n][tx*4+3];
            acc[0][0] += p0*v0; acc[0][1] += p0*v1; acc[0][2] += p0*v2; acc[0][3] += p0*v3;
            acc[1][0] += p1*v0; acc[1][1] += p1*v1; acc[1][2] += p1*v2; acc[1][3] += p1*v3;
            acc[2][0] += p2*v0; acc[2][1] += p2*v1; acc[2][2] += p2*v2; acc[2][3] += p2*v3;
            acc[3][0] += p3*v0; acc[3][1] += p3*v1; acc[3][2] += p3*v2; acc[3][3] += p3*v3;
        }
        __syncthreads();   // before next tile overwrites kT/vS
    }
    #pragma unroll
    for (int i = 0; i < 4; i++) {
        int m = ty * 4 + i;
        int t = (s0 + m) * B_ + b;
        float inv = 1.f / lrow[i];
        #pragma unroll
        for (int j = 0; j < 4; j++)
            o[(size_t)t * D_ + h * DK_ + tx*4 + j] = acc[i][j] * inv;
    }
}

// ---------------- gate / routing ----------------
__global__ void gate_kernel(const float* __restrict__ z,
                            const float* __restrict__ wg,   // [D, E]
                            const float* __restrict__ bg) {
    int t = blockIdx.x;
    int tid = threadIdx.x;
    int w = tid >> 5, lane = tid & 31;
    __shared__ float lg[E_];
    const float* row = z + (size_t)t * D_;
    float s = 0.f;
    for (int i = lane; i < D_; i += 32) s += row[i] * wg[i * E_ + w];
    #pragma unroll
    for (int off = 16; off; off >>= 1) s += __shfl_down_sync(0xffffffffu, s, off);
    if (lane == 0) lg[w] = s + bg[w];
    __syncthreads();
    if (tid == 0) {
        float mx = lg[0]; int am = 0;
        #pragma unroll
        for (int e = 1; e < E_; e++) if (lg[e] > mx) { mx = lg[e]; am = e; }
        float pr[E_], sum = 0.f;
        #pragma unroll
        for (int e = 0; e < E_; e++) { pr[e] = expf(lg[e] - mx); sum += pr[e]; }
        float inv = 1.f / sum;
        #pragma unroll
        for (int e = 0; e < E_; e++) g_probs[t * E_ + e] = pr[e] * inv;
        g_pmax[t] = pr[am] * inv;
        g_route[t] = am;
        int pos = atomicAdd(&g_ecount[am], 1);
        g_etok[am * T_ + pos] = t;
    }
}

// ---------------- route_prob_sum (deterministic) ----------------
__global__ void rps_kernel(float* __restrict__ dout, int out_size) {
    int e = blockIdx.x;
    __shared__ float red[256];
    float s = 0.f;
    for (int t = threadIdx.x; t < T_; t += 256) s += g_probs[t * E_ + e];
    red[threadIdx.x] = s; __syncthreads();
    for (int o = 128; o; o >>= 1) { if (threadIdx.x < o) red[threadIdx.x] += red[threadIdx.x+o]; __syncthreads(); }
    if (threadIdx.x == 0 && out_size >= OUT_TOTAL) dout[(size_t)T_ * D_ + E_ + e] = red[0];
}

// ---------------- tail outputs ----------------
__global__ void tail_kernel(float* __restrict__ dout, int out_size) {
    if (out_size < OUT_TOTAL) return;
    int i = blockIdx.x * blockDim.x + threadIdx.x;
    size_t base = (size_t)T_ * D_;
    if (i < E_) dout[base + i] = (float)g_ecount[i];           // counts
    if (i == 0) dout[base + 2 * E_] = 0.f;                     // n_dropped
    if (i < T_) dout[base + 2 * E_ + 1 + i] = g_pmax[i];       // pmax
}

// ---------------- launch ----------------
extern "C" void kernel_launch(void* const* d_in, const int* in_sizes, int n_in,
                              void* d_out, int out_size) {
    const float* x      = (const float*)d_in[0];
    const float* ln1_g  = (const float*)d_in[1];
    const float* ln1_b  = (const float*)d_in[2];
    const float* ln2_g  = (const float*)d_in[3];
    const float* ln2_b  = (const float*)d_in[4];
    const float* wq     = (const float*)d_in[5];
    const float* bq     = (const float*)d_in[6];
    const float* wk     = (const float*)d_in[7];
    const float* bk     = (const float*)d_in[8];
    const float* wv     = (const float*)d_in[9];
    const float* bv     = (const float*)d_in[10];
    const float* wo     = (const float*)d_in[11];
    const float* bo     = (const float*)d_in[12];
    const float* w_gate = (const float*)d_in[13];
    const float* b_gate = (const float*)d_in[14];
    const float* w1     = (const float*)d_in[15];
    const float* b1     = (const float*)d_in[16];
    const float* w2     = (const float*)d_in[17];
    const float* b2     = (const float*)d_in[18];
    // d_in[19] = mask : all-True by construction, ignored.
    float* out = (float*)d_out;

    float *z1, *q, *k, *v, *o, *x2, *z2, *h;
    int *etok, *ecount;
    cudaGetSymbolAddress((void**)&z1, g_z1);
    cudaGetSymbolAddress((void**)&q,  g_q);
    cudaGetSymbolAddress((void**)&k,  g_k);
    cudaGetSymbolAddress((void**)&v,  g_v);
    cudaGetSymbolAddress((void**)&o,  g_o);
    cudaGetSymbolAddress((void**)&x2, g_x2);
    cudaGetSymbolAddress((void**)&z2, g_z2);
    cudaGetSymbolAddress((void**)&h,  g_h);
    cudaGetSymbolAddress((void**)&etok,   g_etok);
    cudaGetSymbolAddress((void**)&ecount, g_ecount);
    float *pmaxp; cudaGetSymbolAddress((void**)&pmaxp, g_pmax);

    init_kernel<<<1, 32>>>();

    // LN1
    ln_kernel<<<T_, 256>>>(x, ln1_g, ln1_b, z1);

    // QKV projections
    dim3 gP(D_/BN, T_/BM, 1);
    gemm_kernel<<<gP, 256>>>(z1, wq, bq, nullptr, nullptr, q, T_, D_, D_, nullptr, nullptr, 0);
    gemm_kernel<<<gP, 256>>>(z1, wk, bk, nullptr, nullptr, k, T_, D_, D_, nullptr, nullptr, 0);
    gemm_kernel<<<gP, 256>>>(z1, wv, bv, nullptr, nullptr, v, T_, D_, D_, nullptr, nullptr, 0);

    // attention
    attn_kernel<<<dim3(S_/64, B_*H_), 256>>>(q, k, v, o);

    // output projection + residual
    gemm_kernel<<<gP, 256>>>(o, wo, bo, x, nullptr, x2, T_, D_, D_, nullptr, nullptr, 0);

    // LN2
    ln_kernel<<<T_, 256>>>(x2, ln2_g, ln2_b, z2);

    // gate + routing
    gate_kernel<<<T_, 256>>>(z2, w_gate, b_gate);

    // MoE FFN (grouped by expert, top-1 only)
    dim3 g1(F_/BN, T_/BM, E_);
    gemm_kernel<<<g1, 256>>>(z2, w1, b1, nullptr, nullptr, h, T_, F_, D_, etok, ecount, 1);
    dim3 g2(D_/BN, T_/BM, E_);
    gemm_kernel<<<g2, 256>>>(h, w2, b2, x2, pmaxp, out, T_, D_, F_, etok, ecount, 0);

    // aux outputs
    rps_kernel<<<E_, 256>>>(out, out_size);
    tail_kernel<<<(T_ + 255) / 256, 256>>>(out, out_size);
}

// round 3
// speedup vs baseline: 3.4602x; 3.4602x over previous
#include <cuda_runtime.h>
#include <cuda_bf16.h>
#include <math.h>
#include <stdint.h>

// Problem dims
#define S_  2048
#define B_  2
#define D_  1024
#define H_  16
#define DK_ 64
#define E_  8
#define F_  4096
#define T_  (S_*B_)          // 4096 tokens
#define OUT_TOTAL (T_*D_ + E_ + E_ + 1 + T_)

// ---------------- scratch (device globals) ----------------
__device__ float g_z1[T_*D_];
__device__ float g_q [T_*D_];
__device__ float g_k [T_*D_];
__device__ float g_v [T_*D_];
__device__ float g_o [T_*D_];
__device__ float g_x2[T_*D_];
__device__ float g_z2[T_*D_];
__device__ __nv_bfloat16 g_z2b[T_*D_];
__device__ __nv_bfloat16 g_hb[(size_t)T_*F_];
__device__ float g_wqt[D_*D_];
__device__ float g_wkt[D_*D_];
__device__ float g_wvt[D_*D_];
__device__ float g_wot[D_*D_];
__device__ __nv_bfloat16 g_w1t[(size_t)E_*F_*D_];   // [E][F][D]
__device__ __nv_bfloat16 g_w2t[(size_t)E_*D_*F_];   // [E][D][F]
__device__ float g_probs[T_*E_];
__device__ float g_pmax[T_];
__device__ int   g_etok[E_*T_];
__device__ int   g_ecount[E_];

__device__ __forceinline__ uint32_t f2tf32(float f) {
    uint32_t r; asm("cvt.rna.tf32.f32 %0, %1;" : "=r"(r) : "f"(f)); return r;
}
__device__ __forceinline__ void mma_bf16(float* c, const uint32_t* a, uint32_t b0, uint32_t b1) {
    asm volatile("mma.sync.aligned.m16n8k16.row.col.f32.bf16.bf16.f32 "
        "{%0,%1,%2,%3}, {%4,%5,%6,%7}, {%8,%9}, {%0,%1,%2,%3};"
        : "+f"(c[0]), "+f"(c[1]), "+f"(c[2]), "+f"(c[3])
        : "r"(a[0]), "r"(a[1]), "r"(a[2]), "r"(a[3]), "r"(b0), "r"(b1));
}
__device__ __forceinline__ void mma_tf32(float* c, const uint32_t* a, uint32_t b0, uint32_t b1) {
    asm volatile("mma.sync.aligned.m16n8k8.row.col.f32.tf32.tf32.f32 "
        "{%0,%1,%2,%3}, {%4,%5,%6,%7}, {%8,%9}, {%0,%1,%2,%3};"
        : "+f"(c[0]), "+f"(c[1]), "+f"(c[2]), "+f"(c[3])
        : "r"(a[0]), "r"(a[1]), "r"(a[2]), "r"(a[3]), "r"(b0), "r"(b1));
}
__device__ __forceinline__ uint32_t lds32(const char* p) {
    return *(const uint32_t*)p;
}

// ---------------- init ----------------
__global__ void init_kernel() {
    int i = threadIdx.x;
    if (i < E_) g_ecount[i] = 0;
}

// ---------------- LayerNorm (fp32 out + optional bf16 out) ----------------
__global__ void ln_kernel(const float* __restrict__ x,
                          const float* __restrict__ gam,
                          const float* __restrict__ bet,
                          float* __restrict__ z,
                          __nv_bfloat16* __restrict__ zb) {
    int t = blockIdx.x;
    const float* row = x + (size_t)t * D_;
    __shared__ float red[256];
    __shared__ float stats[2];
    float s = 0.f, sq = 0.f;
    for (int i = threadIdx.x; i < D_; i += 256) {
        float v = row[i]; s += v; sq += v * v;
    }
    red[threadIdx.x] = s; __syncthreads();
    for (int o = 128; o; o >>= 1) { if (threadIdx.x < o) red[threadIdx.x] += red[threadIdx.x+o]; __syncthreads(); }
    if (threadIdx.x == 0) stats[0] = red[0];
    __syncthreads();
    red[threadIdx.x] = sq; __syncthreads();
    for (int o = 128; o; o >>= 1) { if (threadIdx.x < o) red[threadIdx.x] += red[threadIdx.x+o]; __syncthreads(); }
    if (threadIdx.x == 0) stats[1] = red[0];
    __syncthreads();
    float mean = stats[0] * (1.f / D_);
    float var  = stats[1] * (1.f / D_) - mean * mean;
    float inv  = rsqrtf(var + 1e-5f);
    for (int i = threadIdx.x; i < D_; i += 256) {
        float v = (row[i] - mean) * inv * gam[i] + bet[i];
        z[(size_t)t * D_ + i] = v;
        if (zb) zb[(size_t)t * D_ + i] = __float2bfloat16(v);
    }
}

// ---------------- transpose (fp32 [R,C] -> fp32/bf16 [C,R]) ----------------
template<bool OB>
__global__ void transpose_k(const float* __restrict__ in, void* __restrict__ out,
                            int R, int C, size_t inB, size_t outB) {
    __shared__ float t[32][33];
    const float* ip = in + (size_t)blockIdx.z * inB;
    int c0 = blockIdx.x * 32, r0 = blockIdx.y * 32;
    int x = threadIdx.x, y = threadIdx.y;
    #pragma unroll
    for (int i = 0; i < 32; i += 8)
        t[y + i][x] = ip[(size_t)(r0 + y + i) * C + c0 + x];
    __syncthreads();
    #pragma unroll
    for (int i = 0; i < 32; i += 8) {
        float v = t[x][y + i];
        if (OB)
            ((__nv_bfloat16*)out)[(size_t)blockIdx.z * outB + (size_t)(c0 + y + i) * R + r0 + x] = __float2bfloat16(v);
        else
            ((float*)out)[(size_t)blockIdx.z * outB + (size_t)(c0 + y + i) * R + r0 + x] = v;
    }
}

// ---------------- mma.sync GEMM: C[tok, n0..] = A[tok,:] @ Wt[n,:]^T ----------------
// EB=4: tf32 (fp32 A/Wt), EB=2: bf16. CTA tile 128x128, chunk = 64B of K per row.
// 8 warps in 4(m) x 2(n); warp tile 32x64; mma m16n8k16(bf16) / m16n8k8(tf32).
#define RB 80   // smem row bytes: 64 data + 16 pad
template<int EB>
__global__ void __launch_bounds__(256)
mma_gemm(const char* __restrict__ A, const char* __restrict__ Wt,
         const float* __restrict__ bias, const float* __restrict__ res,
         const float* __restrict__ rowscale,
         float* __restrict__ Cf, __nv_bfloat16* __restrict__ Cb,
         int M, int N, int K,
         const int* __restrict__ gather, const int* __restrict__ gcount,
         int relu_flag) {
    __shared__ __align__(16) char smA[2][128 * RB];
    __shared__ __align__(16) char smB[2][128 * RB];

    int e  = blockIdx.z;
    int m0 = blockIdx.y * 128, n0 = blockIdx.x * 128;
    const int* glist = nullptr; int mcnt = M;
    if (gather) {
        glist = gather + (size_t)e * T_;
        mcnt  = gcount[e];
        if (m0 >= mcnt) return;
        Wt   += (size_t)e * (size_t)N * K * EB;
        bias += (size_t)e * N;
    }
    int tid = threadIdx.x;
    // staging: each thread owns 2 rows (r, r+64), one uint4 column each, for A and B
    int srow = tid >> 2, c4 = tid & 3;
    int rows[2] = { srow, srow + 64 };
    const char* aptr[2]; bool aval[2];
    const char* bptr[2];
    #pragma unroll
    for (int u = 0; u < 2; u++) {
        int rr = m0 + rows[u]; int tok = rr; aval[u] = true;
        if (gather) { if (rr < mcnt) tok = glist[rr]; else { aval[u] = false; tok = 0; } }
        aptr[u] = A  + (size_t)tok * K * EB + c4 * 16;
        bptr[u] = Wt + (size_t)(n0 + rows[u]) * K * EB + c4 * 16;
    }

    int wid = tid >> 5, lane = tid & 31;
    int wm = wid & 3, wn = wid >> 2;
    int wr = wm * 32, wc = wn * 64;
    int gid = lane >> 2, tig = lane & 3;

    float acc[2][8][4];
    #pragma unroll
    for (int mt = 0; mt < 2; mt++)
        #pragma unroll
        for (int nt = 0; nt < 8; nt++)
            #pragma unroll
            for (int j = 0; j < 4; j++) acc[mt][nt][j] = 0.f;

    int nch = (K * EB) / 64;

    // prologue: stage chunk 0
    {
        uint4 ra[2], rb[2];
        #pragma unroll
        for (int u = 0; u < 2; u++) {
            ra[u] = aval[u] ? *(const uint4*)(aptr[u]) : make_uint4(0,0,0,0);
            rb[u] = *(const uint4*)(bptr[u]);
            if (EB == 4) {
                ra[u].x = f2tf32(__uint_as_float(ra[u].x)); ra[u].y = f2tf32(__uint_as_float(ra[u].y));
                ra[u].z = f2tf32(__uint_as_float(ra[u].z)); ra[u].w = f2tf32(__uint_as_float(ra[u].w));
                rb[u].x = f2tf32(__uint_as_float(rb[u].x)); rb[u].y = f2tf32(__uint_as_float(rb[u].y));
                rb[u].z = f2tf32(__uint_as_float(rb[u].z)); rb[u].w = f2tf32(__uint_as_float(rb[u].w));
            }
            *(uint4*)&smA[0][rows[u] * RB + c4 * 16] = ra[u];
            *(uint4*)&smB[0][rows[u] * RB + c4 * 16] = rb[u];
        }
    }
    __syncthreads();

    for (int i = 0; i < nch; i++) {
        int buf = i & 1;
        uint4 ra[2], rb[2];
        bool more = (i + 1 < nch);
        if (more) {
            size_t kb = (size_t)(i + 1) * 64;
            #pragma unroll
            for (int u = 0; u < 2; u++) {
                ra[u] = aval[u] ? *(const uint4*)(aptr[u] + kb) : make_uint4(0,0,0,0);
                rb[u] = *(const uint4*)(bptr[u] + kb);
                if (EB == 4) {
                    ra[u].x = f2tf32(__uint_as_float(ra[u].x)); ra[u].y = f2tf32(__uint_as_float(ra[u].y));
                    ra[u].z = f2tf32(__uint_as_float(ra[u].z)); ra[u].w = f2tf32(__uint_as_float(ra[u].w));
                    rb[u].x = f2tf32(__uint_as_float(rb[u].x)); rb[u].y = f2tf32(__uint_as_float(rb[u].y));
                    rb[u].z = f2tf32(__uint_as_float(rb[u].z)); rb[u].w = f2tf32(__uint_as_float(rb[u].w));
                }
            }
        }
        // compute on buf
        #pragma unroll
        for (int ks = 0; ks < 2; ks++) {
            uint32_t afr[2][4];
            if (EB == 2) {
                int kb0 = (ks * 16 + tig * 2) * 2;   // byte offset of k element
                #pragma unroll
                for (int mt = 0; mt < 2; mt++) {
                    const char* ap = &smA[buf][(wr + mt * 16 + gid) * RB + kb0];
                    afr[mt][0] = lds32(ap);
                    afr[mt][1] = lds32(ap + 8 * RB);
                    afr[mt][2] = lds32(ap + 16);
                    afr[mt][3] = lds32(ap + 8 * RB + 16);
                }
                #pragma unroll
                for (int nt = 0; nt < 8; nt++) {
                    const char* bp = &smB[buf][(wc + nt * 8 + gid) * RB + kb0];
                    uint32_t b0 = lds32(bp), b1 = lds32(bp + 16);
                    mma_bf16(acc[0][nt], afr[0], b0, b1);
                    mma_bf16(acc[1][nt], afr[1], b0, b1);
                }
            } else {
                int kb0 = (ks * 8 + tig) * 4;
                #pragma unroll
                for (int mt = 0; mt < 2; mt++) {
                    const char* ap = &smA[buf][(wr + mt * 16 + gid) * RB + kb0];
                    afr[mt][0] = lds32(ap);
                    afr[mt][1] = lds32(ap + 8 * RB);
                    afr[mt][2] = lds32(ap + 16);
                    afr[mt][3] = lds32(ap + 8 * RB + 16);
                }
                #pragma unroll
                for (int nt = 0; nt < 8; nt++) {
                    const char* bp = &smB[buf][(wc + nt * 8 + gid) * RB + kb0];
                    uint32_t b0 = lds32(bp), b1 = lds32(bp + 16);
                    mma_tf32(acc[0][nt], afr[0], b0, b1);
                    mma_tf32(acc[1][nt], afr[1], b0, b1);
                }
            }
        }
        if (more) {
            int nb = buf ^ 1;
            #pragma unroll
            for (int u = 0; u < 2; u++) {
                *(uint4*)&smA[nb][rows[u] * RB + c4 * 16] = ra[u];
                *(uint4*)&smB[nb][rows[u] * RB + c4 * 16] = rb[u];
            }
        }
        __syncthreads();
    }

    // epilogue
    #pragma unroll
    for (int mt = 0; mt < 2; mt++) {
        #pragma unroll
        for (int half = 0; half < 2; half++) {
            int r = m0 + wr + mt * 16 + gid + half * 8;
            int tok = r; bool valid = true;
            if (gather) { if (r < mcnt) tok = glist[r]; else valid = false; }
            if (!valid) continue;
            float sc = rowscale ? rowscale[tok] : 1.f;
            size_t ob = (size_t)tok * N;
            #pragma unroll
            for (int nt = 0; nt < 8; nt++) {
                int c = n0 + wc + nt * 8 + tig * 2;
                float v0 = acc[mt][nt][half * 2 + 0] + bias[c];
                float v1 = acc[mt][nt][half * 2 + 1] + bias[c + 1];
                if (relu_flag) { v0 = fmaxf(v0, 0.f); v1 = fmaxf(v1, 0.f); }
                v0 *= sc; v1 *= sc;
                if (res) { v0 += res[ob + c]; v1 += res[ob + c + 1]; }
                if (Cb) {
                    Cb[ob + c]     = __float2bfloat16(v0);
                    Cb[ob + c + 1] = __float2bfloat16(v1);
                } else {
                    Cf[ob + c]     = v0;
                    Cf[ob + c + 1] = v1;
                }
            }
        }
    }
}

// ---------------- flash attention (SIMT fp32) ----------------
__global__ void attn_kernel(const float* __restrict__ q,
                            const float* __restrict__ k,
                            const float* __restrict__ v,
                            float* __restrict__ o) {
    __shared__ float qT[DK_][64];
    __shared__ float kT[DK_][64];
    __shared__ float vS[64][DK_];
    int bh = blockIdx.y;
    int b = bh % B_, h = bh / B_;
    int s0 = blockIdx.x * 64;
    int tid = threadIdx.x, tx = tid & 15, ty = tid >> 4;
    const float scale = 0.125f;

    for (int idx = tid; idx < 64 * DK_; idx += 256) {
        int m = idx >> 6, d = idx & 63;
        int t = (s0 + m) * B_ + b;
        qT[d][m] = q[(size_t)t * D_ + h * DK_ + d];
    }
    float acc[4][4], mrow[4], lrow[4];
    #pragma unroll
    for (int i = 0; i < 4; i++) {
        mrow[i] = -INFINITY; lrow[i] = 0.f;
        #pragma unroll
        for (int j = 0; j < 4; j++) acc[i][j] = 0.f;
    }
    __syncthreads();

    for (int n0 = 0; n0 < S_; n0 += 64) {
        for (int idx = tid; idx < 64 * DK_; idx += 256) {
            int n = idx >> 6, d = idx & 63;
            int t = (n0 + n) * B_ + b;
            kT[d][n] = k[(size_t)t * D_ + h * DK_ + d];
            vS[n][d] = v[(size_t)t * D_ + h * DK_ + d];
        }
        __syncthreads();
        float s[4][4];
        #pragma unroll
        for (int i = 0; i < 4; i++)
            #pragma unroll
            for (int j = 0; j < 4; j++) s[i][j] = 0.f;
        for (int d = 0; d < DK_; d++) {
            float a0 = qT[d][ty*4+0], a1 = qT[d][ty*4+1],
                  a2 = qT[d][ty*4+2], a3 = qT[d][ty*4+3];
            float w0 = kT[d][tx*4+0], w1 = kT[d][tx*4+1],
                  w2 = kT[d][tx*4+2], w3 = kT[d][tx*4+3];
            s[0][0] += a0*w0; s[0][1] += a0*w1; s[0][2] += a0*w2; s[0][3] += a0*w3;
            s[1][0] += a1*w0; s[1][1] += a1*w1; s[1][2] += a1*w2; s[1][3] += a1*w3;
            s[2][0] += a2*w0; s[2][1] += a2*w1; s[2][2] += a2*w2; s[2][3] += a2*w3;
            s[3][0] += a3*w0; s[3][1] += a3*w1; s[3][2] += a3*w2; s[3][3] += a3*w3;
        }
        float p[4][4], alpha[4];
        #pragma unroll
        for (int i = 0; i < 4; i++) {
            float mx = -INFINITY;
            #pragma unroll
            for (int j = 0; j < 4; j++) { s[i][j] *= scale; mx = fmaxf(mx, s[i][j]); }
            #pragma unroll
            for (int off = 8; off; off >>= 1)
                mx = fmaxf(mx, __shfl_xor_sync(0xffffffffu, mx, off, 16));
            float newm = fmaxf(mrow[i], mx);
            float ps = 0.f;
            #pragma unroll
            for (int j = 0; j < 4; j++) { p[i][j] = expf(s[i][j] - newm); ps += p[i][j]; }
            #pragma unroll
            for (int off = 8; off; off >>= 1)
                ps += __shfl_xor_sync(0xffffffffu, ps, off, 16);
            alpha[i] = expf(mrow[i] - newm);
            lrow[i] = lrow[i] * alpha[i] + ps;
            mrow[i] = newm;
        }
        __syncthreads();
        float* pS = &kT[0][0];
        #pragma unroll
        for (int i = 0; i < 4; i++) {
            #pragma unroll
            for (int j = 0; j < 4; j++) {
                pS[(ty*4+i)*64 + tx*4+j] = p[i][j];
                acc[i][j] *= alpha[i];
            }
        }
        __syncthreads();
        for (int n = 0; n < 64; n++) {
            float p0 = pS[(ty*4+0)*64+n], p1 = pS[(ty*4+1)*64+n],
                  p2 = pS[(ty*4+2)*64+n], p3 = pS[(ty*4+3)*64+n];
            float v0 = vS[n][tx*4+0], v1 = vS[n][tx*4+1],
                  v2 = vS[n][tx*4+2], v3 = vS[n][tx*4+3];
            acc[0][0] += p0*v0; acc[0][1] += p0*v1; acc[0][2] += p0*v2; acc[0][3] += p0*v3;
            acc[1][0] += p1*v0; acc[1][1] += p1*v1; acc[1][2] += p1*v2; acc[1][3] += p1*v3;
            acc[2][0] += p2*v0; acc[2][1] += p2*v1; acc[2][2] += p2*v2; acc[2][3] += p2*v3;
            acc[3][0] += p3*v0; acc[3][1] += p3*v1; acc[3][2] += p3*v2; acc[3][3] += p3*v3;
        }
        __syncthreads();
    }
    #pragma unroll
    for (int i = 0; i < 4; i++) {
        int m = ty * 4 + i;
        int t = (s0 + m) * B_ + b;
        float inv = 1.f / lrow[i];
        #pragma unroll
        for (int j = 0; j < 4; j++)
            o[(size_t)t * D_ + h * DK_ + tx*4 + j] = acc[i][j] * inv;
    }
}

// ---------------- gate / routing ----------------
__global__ void gate_kernel(const float* __restrict__ z,
                            const float* __restrict__ wg,
                            const float* __restrict__ bg) {
    int t = blockIdx.x;
    int tid = threadIdx.x;
    int w = tid >> 5, lane = tid & 31;
    __shared__ float lg[E_];
    const float* row = z + (size_t)t * D_;
    float s = 0.f;
    for (int i = lane; i < D_; i += 32) s += row[i] * wg[i * E_ + w];
    #pragma unroll
    for (int off = 16; off; off >>= 1) s += __shfl_down_sync(0xffffffffu, s, off);
    if (lane == 0) lg[w] = s + bg[w];
    __syncthreads();
    if (tid == 0) {
        float mx = lg[0]; int am = 0;
        #pragma unroll
        for (int e = 1; e < E_; e++) if (lg[e] > mx) { mx = lg[e]; am = e; }
        float pr[E_], sum = 0.f;
        #pragma unroll
        for (int e = 0; e < E_; e++) { pr[e] = expf(lg[e] - mx); sum += pr[e]; }
        float inv = 1.f / sum;
        #pragma unroll
        for (int e = 0; e < E_; e++) g_probs[t * E_ + e] = pr[e] * inv;
        g_pmax[t] = pr[am] * inv;
        int pos = atomicAdd(&g_ecount[am], 1);
        g_etok[am * T_ + pos] = t;
    }
}

// ---------------- route_prob_sum (deterministic) ----------------
__global__ void rps_kernel(float* __restrict__ dout, int out_size) {
    int e = blockIdx.x;
    __shared__ float red[256];
    float s = 0.f;
    for (int t = threadIdx.x; t < T_; t += 256) s += g_probs[t * E_ + e];
    red[threadIdx.x] = s; __syncthreads();
    for (int o = 128; o; o >>= 1) { if (threadIdx.x < o) red[threadIdx.x] += red[threadIdx.x+o]; __syncthreads(); }
    if (threadIdx.x == 0 && out_size >= OUT_TOTAL) dout[(size_t)T_ * D_ + E_ + e] = red[0];
}

// ---------------- tail outputs ----------------
__global__ void tail_kernel(float* __restrict__ dout, int out_size) {
    if (out_size < OUT_TOTAL) return;
    int i = blockIdx.x * blockDim.x + threadIdx.x;
    size_t base = (size_t)T_ * D_;
    if (i < E_) dout[base + i] = (float)g_ecount[i];
    if (i == 0) dout[base + 2 * E_] = 0.f;
    if (i < T_) dout[base + 2 * E_ + 1 + i] = g_pmax[i];
}

// ---------------- launch ----------------
extern "C" void kernel_launch(void* const* d_in, const int* in_sizes, int n_in,
                              void* d_out, int out_size) {
    const float* x      = (const float*)d_in[0];
    const float* ln1_g  = (const float*)d_in[1];
    const float* ln1_b  = (const float*)d_in[2];
    const float* ln2_g  = (const float*)d_in[3];
    const float* ln2_b  = (const float*)d_in[4];
    const float* wq     = (const float*)d_in[5];
    const float* bq     = (const float*)d_in[6];
    const float* wk     = (const float*)d_in[7];
    const float* bk     = (const float*)d_in[8];
    const float* wv     = (const float*)d_in[9];
    const float* bv     = (const float*)d_in[10];
    const float* wo     = (const float*)d_in[11];
    const float* bo     = (const float*)d_in[12];
    const float* w_gate = (const float*)d_in[13];
    const float* b_gate = (const float*)d_in[14];
    const float* w1     = (const float*)d_in[15];
    const float* b1     = (const float*)d_in[16];
    const float* w2     = (const float*)d_in[17];
    const float* b2     = (const float*)d_in[18];
    float* out = (float*)d_out;

    float *z1, *q, *k, *v, *o, *x2, *z2, *pmaxp;
    float *wqt, *wkt, *wvt, *wot;
    __nv_bfloat16 *z2b, *hb, *w1t, *w2t;
    int *etok, *ecount;
    cudaGetSymbolAddress((void**)&z1,  g_z1);
    cudaGetSymbolAddress((void**)&q,   g_q);
    cudaGetSymbolAddress((void**)&k,   g_k);
    cudaGetSymbolAddress((void**)&v,   g_v);
    cudaGetSymbolAddress((void**)&o,   g_o);
    cudaGetSymbolAddress((void**)&x2,  g_x2);
    cudaGetSymbolAddress((void**)&z2,  g_z2);
    cudaGetSymbolAddress((void**)&z2b, g_z2b);
    cudaGetSymbolAddress((void**)&hb,  g_hb);
    cudaGetSymbolAddress((void**)&wqt, g_wqt);
    cudaGetSymbolAddress((void**)&wkt, g_wkt);
    cudaGetSymbolAddress((void**)&wvt, g_wvt);
    cudaGetSymbolAddress((void**)&wot, g_wot);
    cudaGetSymbolAddress((void**)&w1t, g_w1t);
    cudaGetSymbolAddress((void**)&w2t, g_w2t);
    cudaGetSymbolAddress((void**)&etok,   g_etok);
    cudaGetSymbolAddress((void**)&ecount, g_ecount);
    cudaGetSymbolAddress((void**)&pmaxp,  g_pmax);

    init_kernel<<<1, 32>>>();

    // weight transposes: [K,N] -> [N,K]
    dim3 tb(32, 8);
    transpose_k<false><<<dim3(D_/32, D_/32, 1), tb>>>(wq, wqt, D_, D_, 0, 0);
    transpose_k<false><<<dim3(D_/32, D_/32, 1), tb>>>(wk, wkt, D_, D_, 0, 0);
    transpose_k<false><<<dim3(D_/32, D_/32, 1), tb>>>(wv, wvt, D_, D_, 0, 0);
    transpose_k<false><<<dim3(D_/32, D_/32, 1), tb>>>(wo, wot, D_, D_, 0, 0);
    transpose_k<true ><<<dim3(F_/32, D_/32, E_), tb>>>(w1, w1t, D_, F_, (size_t)D_*F_, (size_t)D_*F_);
    transpose_k<true ><<<dim3(D_/32, F_/32, E_), tb>>>(w2, w2t, F_, D_, (size_t)F_*D_, (size_t)F_*D_);

    // LN1 (fp32; tf32 GEMM reads fp32)
    ln_kernel<<<T_, 256>>>(x, ln1_g, ln1_b, z1, nullptr);

    // QKV projections (tf32 mma.sync)
    dim3 gP(D_/128, T_/128, 1);
    mma_gemm<4><<<gP, 256>>>((const char*)z1, (const char*)wqt, bq, nullptr, nullptr, q, nullptr, T_, D_, D_, nullptr, nullptr, 0);
    mma_gemm<4><<<gP, 256>>>((const char*)z1, (const char*)wkt, bk, nullptr, nullptr, k, nullptr, T_, D_, D_, nullptr, nullptr, 0);
    mma_gemm<4><<<gP, 256>>>((const char*)z1, (const char*)wvt, bv, nullptr, nullptr, v, nullptr, T_, D_, D_, nullptr, nullptr, 0);

    // attention (fp32 SIMT)
    attn_kernel<<<dim3(S_/64, B_*H_), 256>>>(q, k, v, o);

    // output projection + residual (tf32)
    mma_gemm<4><<<gP, 256>>>((const char*)o, (const char*)wot, bo, x, nullptr, x2, nullptr, T_, D_, D_, nullptr, nullptr, 0);

    // LN2 (fp32 for gate + bf16 for MoE)
    ln_kernel<<<T_, 256>>>(x2, ln2_g, ln2_b, z2, z2b);

    // gate + routing
    gate_kernel<<<T_, 256>>>(z2, w_gate, b_gate);

    // MoE FFN (grouped by expert, bf16 mma.sync)
    mma_gemm<2><<<dim3(F_/128, T_/128, E_), 256>>>((const char*)z2b, (const char*)w1t, b1, nullptr, nullptr, nullptr, hb, T_, F_, D_, etok, ecount, 1);
    mma_gemm<2><<<dim3(D_/128, T_/128, E_), 256>>>((const char*)hb, (const char*)w2t, b2, x2, pmaxp, out, nullptr, T_, D_, F_, etok, ecount, 0);

    // aux outputs
    rps_kernel<<<E_, 256>>>(out, out_size);
    tail_kernel<<<(T_ + 255) / 256, 256>>>(out, out_size);
}

// round 5
// speedup vs baseline: 5.1770x; 1.4961x over previous
#include <cuda_runtime.h>
#include <cuda_bf16.h>
#include <math.h>
#include <stdint.h>

// Problem dims
#define S_  2048
#define B_  2
#define D_  1024
#define H_  16
#define DK_ 64
#define E_  8
#define F_  4096
#define T_  (S_*B_)          // 4096 tokens
#define OUT_TOTAL (T_*D_ + E_ + E_ + 1 + T_)

// ---------------- scratch (device globals) ----------------
__device__ float g_z1[T_*D_];
__device__ float g_q [T_*D_];
__device__ float g_k [T_*D_];
__device__ float g_v [T_*D_];
__device__ float g_o [T_*D_];
__device__ float g_x2[T_*D_];
__device__ float g_z2[T_*D_];
__device__ __nv_bfloat16 g_z2b[T_*D_];
__device__ __nv_bfloat16 g_hb[(size_t)T_*F_];
__device__ float g_wqt[D_*D_];
__device__ float g_wkt[D_*D_];
__device__ float g_wvt[D_*D_];
__device__ float g_wot[D_*D_];
__device__ __nv_bfloat16 g_w1t[(size_t)E_*F_*D_];   // [E][F][D]
__device__ __nv_bfloat16 g_w2t[(size_t)E_*D_*F_];   // [E][D][F]
__device__ float g_probs[T_*E_];
__device__ float g_pmax[T_];
__device__ int   g_etok[E_*T_];
__device__ int   g_ecount[E_];

__device__ __forceinline__ uint32_t f2tf32(float f) {
    uint32_t r; asm("cvt.rna.tf32.f32 %0, %1;" : "=r"(r) : "f"(f)); return r;
}
__device__ __forceinline__ void mma_bf16(float* c, const uint32_t* a, uint32_t b0, uint32_t b1) {
    asm volatile("mma.sync.aligned.m16n8k16.row.col.f32.bf16.bf16.f32 "
        "{%0,%1,%2,%3}, {%4,%5,%6,%7}, {%8,%9}, {%0,%1,%2,%3};"
        : "+f"(c[0]), "+f"(c[1]), "+f"(c[2]), "+f"(c[3])
        : "r"(a[0]), "r"(a[1]), "r"(a[2]), "r"(a[3]), "r"(b0), "r"(b1));
}
__device__ __forceinline__ void mma_tf32(float* c, const uint32_t* a, uint32_t b0, uint32_t b1) {
    asm volatile("mma.sync.aligned.m16n8k8.row.col.f32.tf32.tf32.f32 "
        "{%0,%1,%2,%3}, {%4,%5,%6,%7}, {%8,%9}, {%0,%1,%2,%3};"
        : "+f"(c[0]), "+f"(c[1]), "+f"(c[2]), "+f"(c[3])
        : "r"(a[0]), "r"(a[1]), "r"(a[2]), "r"(a[3]), "r"(b0), "r"(b1));
}
__device__ __forceinline__ uint32_t lds32(const char* p) {
    return *(const uint32_t*)p;
}

// ---------------- init ----------------
__global__ void init_kernel() {
    int i = threadIdx.x;
    if (i < E_) g_ecount[i] = 0;
}

// ---------------- LayerNorm (fp32 out + optional bf16 out) ----------------
__global__ void ln_kernel(const float* __restrict__ x,
                          const float* __restrict__ gam,
                          const float* __restrict__ bet,
                          float* __restrict__ z,
                          __nv_bfloat16* __restrict__ zb) {
    int t = blockIdx.x;
    const float* row = x + (size_t)t * D_;
    __shared__ float red[256];
    __shared__ float stats[2];
    float s = 0.f, sq = 0.f;
    for (int i = threadIdx.x; i < D_; i += 256) {
        float v = row[i]; s += v; sq += v * v;
    }
    red[threadIdx.x] = s; __syncthreads();
    for (int o = 128; o; o >>= 1) { if (threadIdx.x < o) red[threadIdx.x] += red[threadIdx.x+o]; __syncthreads(); }
    if (threadIdx.x == 0) stats[0] = red[0];
    __syncthreads();
    red[threadIdx.x] = sq; __syncthreads();
    for (int o = 128; o; o >>= 1) { if (threadIdx.x < o) red[threadIdx.x] += red[threadIdx.x+o]; __syncthreads(); }
    if (threadIdx.x == 0) stats[1] = red[0];
    __syncthreads();
    float mean = stats[0] * (1.f / D_);
    float var  = stats[1] * (1.f / D_) - mean * mean;
    float inv  = rsqrtf(var + 1e-5f);
    for (int i = threadIdx.x; i < D_; i += 256) {
        float v = (row[i] - mean) * inv * gam[i] + bet[i];
        z[(size_t)t * D_ + i] = v;
        if (zb) zb[(size_t)t * D_ + i] = __float2bfloat16(v);
    }
}

// ---------------- transpose (fp32 [R,C] -> fp32/bf16 [C,R]) ----------------
template<bool OB>
__global__ void transpose_k(const float* __restrict__ in, void* __restrict__ out,
                            int R, int C, size_t inB, size_t outB) {
    __shared__ float t[32][33];
    const float* ip = in + (size_t)blockIdx.z * inB;
    int c0 = blockIdx.x * 32, r0 = blockIdx.y * 32;
    int x = threadIdx.x, y = threadIdx.y;
    #pragma unroll
    for (int i = 0; i < 32; i += 8)
        t[y + i][x] = ip[(size_t)(r0 + y + i) * C + c0 + x];
    __syncthreads();
    #pragma unroll
    for (int i = 0; i < 32; i += 8) {
        float v = t[x][y + i];
        if (OB)
            ((__nv_bfloat16*)out)[(size_t)blockIdx.z * outB + (size_t)(c0 + y + i) * R + r0 + x] = __float2bfloat16(v);
        else
            ((float*)out)[(size_t)blockIdx.z * outB + (size_t)(c0 + y + i) * R + r0 + x] = v;
    }
}

// ---------------- mma.sync GEMM (unchanged from R3) ----------------
#define RB 80   // smem row bytes: 64 data + 16 pad
template<int EB>
__global__ void __launch_bounds__(256)
mma_gemm(const char* __restrict__ A, const char* __restrict__ Wt,
         const float* __restrict__ bias, const float* __restrict__ res,
         const float* __restrict__ rowscale,
         float* __restrict__ Cf, __nv_bfloat16* __restrict__ Cb,
         int M, int N, int K,
         const int* __restrict__ gather, const int* __restrict__ gcount,
         int relu_flag) {
    __shared__ __align__(16) char smA[2][128 * RB];
    __shared__ __align__(16) char smB[2][128 * RB];

    int e  = blockIdx.z;
    int m0 = blockIdx.y * 128, n0 = blockIdx.x * 128;
    const int* glist = nullptr; int mcnt = M;
    if (gather) {
        glist = gather + (size_t)e * T_;
        mcnt  = gcount[e];
        if (m0 >= mcnt) return;
        Wt   += (size_t)e * (size_t)N * K * EB;
        bias += (size_t)e * N;
    }
    int tid = threadIdx.x;
    int srow = tid >> 2, c4 = tid & 3;
    int rows[2] = { srow, srow + 64 };
    const char* aptr[2]; bool aval[2];
    const char* bptr[2];
    #pragma unroll
    for (int u = 0; u < 2; u++) {
        int rr = m0 + rows[u]; int tok = rr; aval[u] = true;
        if (gather) { if (rr < mcnt) tok = glist[rr]; else { aval[u] = false; tok = 0; } }
        aptr[u] = A  + (size_t)tok * K * EB + c4 * 16;
        bptr[u] = Wt + (size_t)(n0 + rows[u]) * K * EB + c4 * 16;
    }

    int wid = tid >> 5, lane = tid & 31;
    int wm = wid & 3, wn = wid >> 2;
    int wr = wm * 32, wc = wn * 64;
    int gid = lane >> 2, tig = lane & 3;

    float acc[2][8][4];
    #pragma unroll
    for (int mt = 0; mt < 2; mt++)
        #pragma unroll
        for (int nt = 0; nt < 8; nt++)
            #pragma unroll
            for (int j = 0; j < 4; j++) acc[mt][nt][j] = 0.f;

    int nch = (K * EB) / 64;

    {
        uint4 ra[2], rb[2];
        #pragma unroll
        for (int u = 0; u < 2; u++) {
            ra[u] = aval[u] ? *(const uint4*)(aptr[u]) : make_uint4(0,0,0,0);
            rb[u] = *(const uint4*)(bptr[u]);
            if (EB == 4) {
                ra[u].x = f2tf32(__uint_as_float(ra[u].x)); ra[u].y = f2tf32(__uint_as_float(ra[u].y));
                ra[u].z = f2tf32(__uint_as_float(ra[u].z)); ra[u].w = f2tf32(__uint_as_float(ra[u].w));
                rb[u].x = f2tf32(__uint_as_float(rb[u].x)); rb[u].y = f2tf32(__uint_as_float(rb[u].y));
                rb[u].z = f2tf32(__uint_as_float(rb[u].z)); rb[u].w = f2tf32(__uint_as_float(rb[u].w));
            }
            *(uint4*)&smA[0][rows[u] * RB + c4 * 16] = ra[u];
            *(uint4*)&smB[0][rows[u] * RB + c4 * 16] = rb[u];
        }
    }
    __syncthreads();

    for (int i = 0; i < nch; i++) {
        int buf = i & 1;
        uint4 ra[2], rb[2];
        bool more = (i + 1 < nch);
        if (more) {
            size_t kb = (size_t)(i + 1) * 64;
            #pragma unroll
            for (int u = 0; u < 2; u++) {
                ra[u] = aval[u] ? *(const uint4*)(aptr[u] + kb) : make_uint4(0,0,0,0);
                rb[u] = *(const uint4*)(bptr[u] + kb);
                if (EB == 4) {
                    ra[u].x = f2tf32(__uint_as_float(ra[u].x)); ra[u].y = f2tf32(__uint_as_float(ra[u].y));
                    ra[u].z = f2tf32(__uint_as_float(ra[u].z)); ra[u].w = f2tf32(__uint_as_float(ra[u].w));
                    rb[u].x = f2tf32(__uint_as_float(rb[u].x)); rb[u].y = f2tf32(__uint_as_float(rb[u].y));
                    rb[u].z = f2tf32(__uint_as_float(rb[u].z)); rb[u].w = f2tf32(__uint_as_float(rb[u].w));
                }
            }
        }
        #pragma unroll
        for (int ks = 0; ks < 2; ks++) {
            uint32_t afr[2][4];
            if (EB == 2) {
                int kb0 = (ks * 16 + tig * 2) * 2;
                #pragma unroll
                for (int mt = 0; mt < 2; mt++) {
                    const char* ap = &smA[buf][(wr + mt * 16 + gid) * RB + kb0];
                    afr[mt][0] = lds32(ap);
                    afr[mt][1] = lds32(ap + 8 * RB);
                    afr[mt][2] = lds32(ap + 16);
                    afr[mt][3] = lds32(ap + 8 * RB + 16);
                }
                #pragma unroll
                for (int nt = 0; nt < 8; nt++) {
                    const char* bp = &smB[buf][(wc + nt * 8 + gid) * RB + kb0];
                    uint32_t b0 = lds32(bp), b1 = lds32(bp + 16);
                    mma_bf16(acc[0][nt], afr[0], b0, b1);
                    mma_bf16(acc[1][nt], afr[1], b0, b1);
                }
            } else {
                int kb0 = (ks * 8 + tig) * 4;
                #pragma unroll
                for (int mt = 0; mt < 2; mt++) {
                    const char* ap = &smA[buf][(wr + mt * 16 + gid) * RB + kb0];
                    afr[mt][0] = lds32(ap);
                    afr[mt][1] = lds32(ap + 8 * RB);
                    afr[mt][2] = lds32(ap + 16);
                    afr[mt][3] = lds32(ap + 8 * RB + 16);
                }
                #pragma unroll
                for (int nt = 0; nt < 8; nt++) {
                    const char* bp = &smB[buf][(wc + nt * 8 + gid) * RB + kb0];
                    uint32_t b0 = lds32(bp), b1 = lds32(bp + 16);
                    mma_tf32(acc[0][nt], afr[0], b0, b1);
                    mma_tf32(acc[1][nt], afr[1], b0, b1);
                }
            }
        }
        if (more) {
            int nb = buf ^ 1;
            #pragma unroll
            for (int u = 0; u < 2; u++) {
                *(uint4*)&smA[nb][rows[u] * RB + c4 * 16] = ra[u];
                *(uint4*)&smB[nb][rows[u] * RB + c4 * 16] = rb[u];
            }
        }
        __syncthreads();
    }

    #pragma unroll
    for (int mt = 0; mt < 2; mt++) {
        #pragma unroll
        for (int half = 0; half < 2; half++) {
            int r = m0 + wr + mt * 16 + gid + half * 8;
            int tok = r; bool valid = true;
            if (gather) { if (r < mcnt) tok = glist[r]; else valid = false; }
            if (!valid) continue;
            float sc = rowscale ? rowscale[tok] : 1.f;
            size_t ob = (size_t)tok * N;
            #pragma unroll
            for (int nt = 0; nt < 8; nt++) {
                int c = n0 + wc + nt * 8 + tig * 2;
                float v0 = acc[mt][nt][half * 2 + 0] + bias[c];
                float v1 = acc[mt][nt][half * 2 + 1] + bias[c + 1];
                if (relu_flag) { v0 = fmaxf(v0, 0.f); v1 = fmaxf(v1, 0.f); }
                v0 *= sc; v1 *= sc;
                if (res) { v0 += res[ob + c]; v1 += res[ob + c + 1]; }
                if (Cb) {
                    Cb[ob + c]     = __float2bfloat16(v0);
                    Cb[ob + c + 1] = __float2bfloat16(v1);
                } else {
                    Cf[ob + c]     = v0;
                    Cf[ob + c + 1] = v1;
                }
            }
        }
    }
}

// ---------------- flash attention via mma.sync tf32 ----------------
// CTA: 64 q-rows of one (b,h); 4 warps x 16 rows; K tiles of 64; DK=64.
#define APAD 68   // words per smem row
#define ATTN_SMEM (256 * APAD * 4)   // qS,kS,vT (64 rows each) + pS (4*16 rows)
__global__ void __launch_bounds__(128)
attn_mma(const float* __restrict__ q, const float* __restrict__ k,
         const float* __restrict__ v, float* __restrict__ o) {
    extern __shared__ uint32_t sm[];
    uint32_t* qS = sm;                  // [64][APAD]
    uint32_t* kS = qS + 64 * APAD;      // [64][APAD]
    uint32_t* vT = kS + 64 * APAD;      // [d][key]
    uint32_t* pS = vT + 64 * APAD;      // [4*16][APAD]

    int bh = blockIdx.y;
    int b = bh % B_, h = bh / B_;
    int s0 = blockIdx.x * 64;
    int tid = threadIdx.x, lane = tid & 31, wid = tid >> 5;
    int gid = lane >> 2, tig = lane & 3;
    int wr = wid * 16;
    const float scale = 0.125f;

    // stage Q (tf32)
    int lr = tid >> 1, lc0 = (tid & 1) * 32;
    {
        int t = (s0 + lr) * B_ + b;
        const float* qp = q + (size_t)t * D_ + h * DK_ + lc0;
        #pragma unroll
        for (int j = 0; j < 8; j++) {
            float4 f = *(const float4*)(qp + j * 4);
            *(uint4*)&qS[lr * APAD + lc0 + j * 4] =
                make_uint4(f2tf32(f.x), f2tf32(f.y), f2tf32(f.z), f2tf32(f.w));
        }
    }

    float oacc[8][4];
    #pragma unroll
    for (int dt = 0; dt < 8; dt++)
        #pragma unroll
        for (int j = 0; j < 4; j++) oacc[dt][j] = 0.f;
    float mrow0 = -INFINITY, mrow1 = -INFINITY, lrow0 = 0.f, lrow1 = 0.f;

    for (int n0 = 0; n0 < S_; n0 += 64) {
        // stage K, V^T (tf32)
        {
            int t = (n0 + lr) * B_ + b;
            const float* kp = k + (size_t)t * D_ + h * DK_ + lc0;
            const float* vp = v + (size_t)t * D_ + h * DK_ + lc0;
            #pragma unroll
            for (int j = 0; j < 8; j++) {
                float4 f = *(const float4*)(kp + j * 4);
                *(uint4*)&kS[lr * APAD + lc0 + j * 4] =
                    make_uint4(f2tf32(f.x), f2tf32(f.y), f2tf32(f.z), f2tf32(f.w));
                float4 g = *(const float4*)(vp + j * 4);
                int dc = lc0 + j * 4;
                vT[(dc + 0) * APAD + lr] = f2tf32(g.x);
                vT[(dc + 1) * APAD + lr] = f2tf32(g.y);
                vT[(dc + 2) * APAD + lr] = f2tf32(g.z);
                vT[(dc + 3) * APAD + lr] = f2tf32(g.w);
            }
        }
        __syncthreads();

        // scores: 16x64 per warp
        float sc[8][4];
        #pragma unroll
        for (int nt = 0; nt < 8; nt++)
            #pragma unroll
            for (int j = 0; j < 4; j++) sc[nt][j] = 0.f;
        #pragma unroll
        for (int kk = 0; kk < 8; kk++) {
            uint32_t a[4];
            const uint32_t* ar = &qS[(wr + gid) * APAD + kk * 8 + tig];
            a[0] = ar[0]; a[1] = ar[8 * APAD]; a[2] = ar[4]; a[3] = ar[8 * APAD + 4];
            #pragma unroll
            for (int nt = 0; nt < 8; nt++) {
                const uint32_t* br = &kS[(nt * 8 + gid) * APAD + kk * 8 + tig];
                mma_tf32(sc[nt], a, br[0], br[4]);
            }
        }

        // online softmax (rows r0=wr+gid, r1=r0+8)
        float mx0 = -INFINITY, mx1 = -INFINITY;
        #pragma unroll
        for (int nt = 0; nt < 8; nt++) {
            sc[nt][0] *= scale; sc[nt][1] *= scale; sc[nt][2] *= scale; sc[nt][3] *= scale;
            mx0 = fmaxf(mx0, fmaxf(sc[nt][0], sc[nt][1]));
            mx1 = fmaxf(mx1, fmaxf(sc[nt][2], sc[nt][3]));
        }
        mx0 = fmaxf(mx0, __shfl_xor_sync(0xffffffffu, mx0, 1));
        mx0 = fmaxf(mx0, __shfl_xor_sync(0xffffffffu, mx0, 2));
        mx1 = fmaxf(mx1, __shfl_xor_sync(0xffffffffu, mx1, 1));
        mx1 = fmaxf(mx1, __shfl_xor_sync(0xffffffffu, mx1, 2));
        float nm0 = fmaxf(mrow0, mx0), nm1 = fmaxf(mrow1, mx1);
        float al0 = __expf(mrow0 - nm0), al1 = __expf(mrow1 - nm1);
        float ps0 = 0.f, ps1 = 0.f;
        uint32_t* pw = pS + wid * 16 * APAD;
        #pragma unroll
        for (int nt = 0; nt < 8; nt++) {
            float p0 = __expf(sc[nt][0] - nm0);
            float p1 = __expf(sc[nt][1] - nm0);
            float p2 = __expf(sc[nt][2] - nm1);
            float p3 = __expf(sc[nt][3] - nm1);
            ps0 += p0 + p1; ps1 += p2 + p3;
            int c = nt * 8 + tig * 2;
            pw[gid * APAD + c]           = f2tf32(p0);
            pw[gid * APAD + c + 1]       = f2tf32(p1);
            pw[(gid + 8) * APAD + c]     = f2tf32(p2);
            pw[(gid + 8) * APAD + c + 1] = f2tf32(p3);
        }
        ps0 += __shfl_xor_sync(0xffffffffu, ps0, 1);
        ps0 += __shfl_xor_sync(0xffffffffu, ps0, 2);
        ps1 += __shfl_xor_sync(0xffffffffu, ps1, 1);
        ps1 += __shfl_xor_sync(0xffffffffu, ps1, 2);
        lrow0 = lrow0 * al0 + ps0; mrow0 = nm0;
        lrow1 = lrow1 * al1 + ps1; mrow1 = nm1;
        #pragma unroll
        for (int dt = 0; dt < 8; dt++) {
            oacc[dt][0] *= al0; oacc[dt][1] *= al0;
            oacc[dt][2] *= al1; oacc[dt][3] *= al1;
        }
        __syncwarp();

        // P @ V : A from pS (own warp), B from vT
        #pragma unroll
        for (int kk = 0; kk < 8; kk++) {
            uint32_t a[4];
            const uint32_t* ar = &pw[gid * APAD + kk * 8 + tig];
            a[0] = ar[0]; a[1] = ar[8 * APAD]; a[2] = ar[4]; a[3] = ar[8 * APAD + 4];
            #pragma unroll
            for (int dt = 0; dt < 8; dt++) {
                const uint32_t* br = &vT[(dt * 8 + gid) * APAD + kk * 8 + tig];
                mma_tf32(oacc[dt], a, br[0], br[4]);
            }
        }
        __syncthreads();
    }

    // write O
    float inv0 = 1.f / lrow0, inv1 = 1.f / lrow1;
    int r0 = s0 + wr + gid, r1 = r0 + 8;
    size_t o0 = (size_t)(r0 * B_ + b) * D_ + h * DK_;
    size_t o1 = (size_t)(r1 * B_ + b) * D_ + h * DK_;
    #pragma unroll
    for (int dt = 0; dt < 8; dt++) {
        int c = dt * 8 + tig * 2;
        o[o0 + c]     = oacc[dt][0] * inv0;
        o[o0 + c + 1] = oacc[dt][1] * inv0;
        o[o1 + c]     = oacc[dt][2] * inv1;
        o[o1 + c + 1] = oacc[dt][3] * inv1;
    }
}

// ---------------- gate / routing ----------------
__global__ void gate_kernel(const float* __restrict__ z,
                            const float* __restrict__ wg,
                            const float* __restrict__ bg) {
    int t = blockIdx.x;
    int tid = threadIdx.x;
    int w = tid >> 5, lane = tid & 31;
    __shared__ float lg[E_];
    const float* row = z + (size_t)t * D_;
    float s = 0.f;
    for (int i = lane; i < D_; i += 32) s += row[i] * wg[i * E_ + w];
    #pragma unroll
    for (int off = 16; off; off >>= 1) s += __shfl_down_sync(0xffffffffu, s, off);
    if (lane == 0) lg[w] = s + bg[w];
    __syncthreads();
    if (tid == 0) {
        float mx = lg[0]; int am = 0;
        #pragma unroll
        for (int e = 1; e < E_; e++) if (lg[e] > mx) { mx = lg[e]; am = e; }
        float pr[E_], sum = 0.f;
        #pragma unroll
        for (int e = 0; e < E_; e++) { pr[e] = expf(lg[e] - mx); sum += pr[e]; }
        float inv = 1.f / sum;
        #pragma unroll
        for (int e = 0; e < E_; e++) g_probs[t * E_ + e] = pr[e] * inv;
        g_pmax[t] = pr[am] * inv;
        int pos = atomicAdd(&g_ecount[am], 1);
        g_etok[am * T_ + pos] = t;
    }
}

// ---------------- route_prob_sum (deterministic) ----------------
__global__ void rps_kernel(float* __restrict__ dout, int out_size) {
    int e = blockIdx.x;
    __shared__ float red[256];
    float s = 0.f;
    for (int t = threadIdx.x; t < T_; t += 256) s += g_probs[t * E_ + e];
    red[threadIdx.x] = s; __syncthreads();
    for (int o = 128; o; o >>= 1) { if (threadIdx.x < o) red[threadIdx.x] += red[threadIdx.x+o]; __syncthreads(); }
    if (threadIdx.x == 0 && out_size >= OUT_TOTAL) dout[(size_t)T_ * D_ + E_ + e] = red[0];
}

// ---------------- tail outputs ----------------
__global__ void tail_kernel(float* __restrict__ dout, int out_size) {
    if (out_size < OUT_TOTAL) return;
    int i = blockIdx.x * blockDim.x + threadIdx.x;
    size_t base = (size_t)T_ * D_;
    if (i < E_) dout[base + i] = (float)g_ecount[i];
    if (i == 0) dout[base + 2 * E_] = 0.f;
    if (i < T_) dout[base + 2 * E_ + 1 + i] = g_pmax[i];
}

// ---------------- launch ----------------
extern "C" void kernel_launch(void* const* d_in, const int* in_sizes, int n_in,
                              void* d_out, int out_size) {
    const float* x      = (const float*)d_in[0];
    const float* ln1_g  = (const float*)d_in[1];
    const float* ln1_b  = (const float*)d_in[2];
    const float* ln2_g  = (const float*)d_in[3];
    const float* ln2_b  = (const float*)d_in[4];
    const float* wq     = (const float*)d_in[5];
    const float* bq     = (const float*)d_in[6];
    const float* wk     = (const float*)d_in[7];
    const float* bk     = (const float*)d_in[8];
    const float* wv     = (const float*)d_in[9];
    const float* bv     = (const float*)d_in[10];
    const float* wo     = (const float*)d_in[11];
    const float* bo     = (const float*)d_in[12];
    const float* w_gate = (const float*)d_in[13];
    const float* b_gate = (const float*)d_in[14];
    const float* w1     = (const float*)d_in[15];
    const float* b1     = (const float*)d_in[16];
    const float* w2     = (const float*)d_in[17];
    const float* b2     = (const float*)d_in[18];
    float* out = (float*)d_out;

    float *z1, *q, *k, *v, *o, *x2, *z2, *pmaxp;
    float *wqt, *wkt, *wvt, *wot;
    __nv_bfloat16 *z2b, *hb, *w1t, *w2t;
    int *etok, *ecount;
    cudaGetSymbolAddress((void**)&z1,  g_z1);
    cudaGetSymbolAddress((void**)&q,   g_q);
    cudaGetSymbolAddress((void**)&k,   g_k);
    cudaGetSymbolAddress((void**)&v,   g_v);
    cudaGetSymbolAddress((void**)&o,   g_o);
    cudaGetSymbolAddress((void**)&x2,  g_x2);
    cudaGetSymbolAddress((void**)&z2,  g_z2);
    cudaGetSymbolAddress((void**)&z2b, g_z2b);
    cudaGetSymbolAddress((void**)&hb,  g_hb);
    cudaGetSymbolAddress((void**)&wqt, g_wqt);
    cudaGetSymbolAddress((void**)&wkt, g_wkt);
    cudaGetSymbolAddress((void**)&wvt, g_wvt);
    cudaGetSymbolAddress((void**)&wot, g_wot);
    cudaGetSymbolAddress((void**)&w1t, g_w1t);
    cudaGetSymbolAddress((void**)&w2t, g_w2t);
    cudaGetSymbolAddress((void**)&etok,   g_etok);
    cudaGetSymbolAddress((void**)&ecount, g_ecount);
    cudaGetSymbolAddress((void**)&pmaxp,  g_pmax);

    cudaFuncSetAttribute(attn_mma, cudaFuncAttributeMaxDynamicSharedMemorySize, ATTN_SMEM);

    init_kernel<<<1, 32>>>();

    // weight transposes: [K,N] -> [N,K]
    dim3 tb(32, 8);
    transpose_k<false><<<dim3(D_/32, D_/32, 1), tb>>>(wq, wqt, D_, D_, 0, 0);
    transpose_k<false><<<dim3(D_/32, D_/32, 1), tb>>>(wk, wkt, D_, D_, 0, 0);
    transpose_k<false><<<dim3(D_/32, D_/32, 1), tb>>>(wv, wvt, D_, D_, 0, 0);
    transpose_k<false><<<dim3(D_/32, D_/32, 1), tb>>>(wo, wot, D_, D_, 0, 0);
    transpose_k<true ><<<dim3(F_/32, D_/32, E_), tb>>>(w1, w1t, D_, F_, (size_t)D_*F_, (size_t)D_*F_);
    transpose_k<true ><<<dim3(D_/32, F_/32, E_), tb>>>(w2, w2t, F_, D_, (size_t)F_*D_, (size_t)F_*D_);

    // LN1
    ln_kernel<<<T_, 256>>>(x, ln1_g, ln1_b, z1, nullptr);

    // QKV projections (tf32 mma.sync)
    dim3 gP(D_/128, T_/128, 1);
    mma_gemm<4><<<gP, 256>>>((const char*)z1, (const char*)wqt, bq, nullptr, nullptr, q, nullptr, T_, D_, D_, nullptr, nullptr, 0);
    mma_gemm<4><<<gP, 256>>>((const char*)z1, (const char*)wkt, bk, nullptr, nullptr, k, nullptr, T_, D_, D_, nullptr, nullptr, 0);
    mma_gemm<4><<<gP, 256>>>((const char*)z1, (const char*)wvt, bv, nullptr, nullptr, v, nullptr, T_, D_, D_, nullptr, nullptr, 0);

    // attention (tf32 mma.sync flash)
    attn_mma<<<dim3(S_/64, B_*H_), 128, ATTN_SMEM>>>(q, k, v, o);

    // output projection + residual (tf32)
    mma_gemm<4><<<gP, 256>>>((const char*)o, (const char*)wot, bo, x, nullptr, x2, nullptr, T_, D_, D_, nullptr, nullptr, 0);

    // LN2
    ln_kernel<<<T_, 256>>>(x2, ln2_g, ln2_b, z2, z2b);

    // gate + routing
    gate_kernel<<<T_, 256>>>(z2, w_gate, b_gate);

    // MoE FFN (grouped by expert, bf16 mma.sync)
    mma_gemm<2><<<dim3(F_/128, T_/128, E_), 256>>>((const char*)z2b, (const char*)w1t, b1, nullptr, nullptr, nullptr, hb, T_, F_, D_, etok, ecount, 1);
    mma_gemm<2><<<dim3(D_/128, T_/128, E_), 256>>>((const char*)hb, (const char*)w2t, b2, x2, pmaxp, out, nullptr, T_, D_, F_, etok, ecount, 0);

    // aux outputs
    rps_kernel<<<E_, 256>>>(out, out_size);
    tail_kernel<<<(T_ + 255) / 256, 256>>>(out, out_size);
}

// round 6
// speedup vs baseline: 6.6139x; 1.2776x over previous
#include <cuda_runtime.h>
#include <cuda_bf16.h>
#include <math.h>
#include <stdint.h>

// Problem dims
#define S_  2048
#define B_  2
#define D_  1024
#define H_  16
#define DK_ 64
#define E_  8
#define F_  4096
#define T_  (S_*B_)          // 4096 tokens
#define OUT_TOTAL (T_*D_ + E_ + E_ + 1 + T_)

// ---------------- scratch (device globals) ----------------
__device__ float g_z1[T_*D_];
__device__ float g_qkv[(size_t)T_*3072];
__device__ float g_o [T_*D_];
__device__ float g_x2[T_*D_];
__device__ float g_z2[T_*D_];
__device__ __nv_bfloat16 g_z2b[T_*D_];
__device__ __nv_bfloat16 g_hb[(size_t)T_*F_];
__device__ float g_probs[T_*E_];
__device__ float g_pmax[T_];
__device__ int   g_etok[E_*T_];
__device__ int   g_ecount[E_];

__device__ __forceinline__ uint32_t f2tf32(float f) {
    uint32_t r; asm("cvt.rna.tf32.f32 %0, %1;" : "=r"(r) : "f"(f)); return r;
}
__device__ __forceinline__ uint32_t packbf(float lo, float hi) {
    __nv_bfloat162 t = __floats2bfloat162_rn(lo, hi);
    return *(uint32_t*)&t;
}
__device__ __forceinline__ void mma_bf16(float* c, const uint32_t* a, uint32_t b0, uint32_t b1) {
    asm volatile("mma.sync.aligned.m16n8k16.row.col.f32.bf16.bf16.f32 "
        "{%0,%1,%2,%3}, {%4,%5,%6,%7}, {%8,%9}, {%0,%1,%2,%3};"
        : "+f"(c[0]), "+f"(c[1]), "+f"(c[2]), "+f"(c[3])
        : "r"(a[0]), "r"(a[1]), "r"(a[2]), "r"(a[3]), "r"(b0), "r"(b1));
}
__device__ __forceinline__ void mma_tf32(float* c, const uint32_t* a, uint32_t b0, uint32_t b1) {
    asm volatile("mma.sync.aligned.m16n8k8.row.col.f32.tf32.tf32.f32 "
        "{%0,%1,%2,%3}, {%4,%5,%6,%7}, {%8,%9}, {%0,%1,%2,%3};"
        : "+f"(c[0]), "+f"(c[1]), "+f"(c[2]), "+f"(c[3])
        : "r"(a[0]), "r"(a[1]), "r"(a[2]), "r"(a[3]), "r"(b0), "r"(b1));
}
__device__ __forceinline__ uint32_t lds32(const char* p) {
    return *(const uint32_t*)p;
}

// ---------------- init ----------------
__global__ void init_kernel() {
    int i = threadIdx.x;
    if (i < E_) g_ecount[i] = 0;
}

// ---------------- LayerNorm (fp32 out + optional bf16 out) ----------------
__global__ void ln_kernel(const float* __restrict__ x,
                          const float* __restrict__ gam,
                          const float* __restrict__ bet,
                          float* __restrict__ z,
                          __nv_bfloat16* __restrict__ zb) {
    int t = blockIdx.x;
    const float* row = x + (size_t)t * D_;
    __shared__ float red[256];
    __shared__ float stats[2];
    float s = 0.f, sq = 0.f;
    for (int i = threadIdx.x; i < D_; i += 256) {
        float v = row[i]; s += v; sq += v * v;
    }
    red[threadIdx.x] = s; __syncthreads();
    for (int o = 128; o; o >>= 1) { if (threadIdx.x < o) red[threadIdx.x] += red[threadIdx.x+o]; __syncthreads(); }
    if (threadIdx.x == 0) stats[0] = red[0];
    __syncthreads();
    red[threadIdx.x] = sq; __syncthreads();
    for (int o = 128; o; o >>= 1) { if (threadIdx.x < o) red[threadIdx.x] += red[threadIdx.x+o]; __syncthreads(); }
    if (threadIdx.x == 0) stats[1] = red[0];
    __syncthreads();
    float mean = stats[0] * (1.f / D_);
    float var  = stats[1] * (1.f / D_) - mean * mean;
    float inv  = rsqrtf(var + 1e-5f);
    for (int i = threadIdx.x; i < D_; i += 256) {
        float v = (row[i] - mean) * inv * gam[i] + bet[i];
        z[(size_t)t * D_ + i] = v;
        if (zb) zb[(size_t)t * D_ + i] = __float2bfloat16(v);
    }
}

// ---------------- mma.sync GEMM with direct row-major B ----------------
// C[tok, n] = A[tok,:K] @ B[:K, n] (+bias, relu, rowscale, residual).
// A: EB=4 fp32 (tf32 math) or EB=2 bf16. B: always fp32 [K][Nb] row-major,
// converted in-staging. smB layout: [16 k-rows][136 words] per chunk, where a
// "k-row" is one k (tf32) or a k-pair packed bf16x2 (bf16). Row stride 136
// (mod 32 = 8) makes B fragment loads conflict-free.
// QKV mode: B1 != null -> N=3072 split over B0/B1/B2 each [K][1024].
#define RB 80   // smem A row bytes
template<int EB>
__global__ void __launch_bounds__(256)
mma_gemm(const char* __restrict__ A,
         const float* __restrict__ B0, const float* __restrict__ B1, const float* __restrict__ B2,
         const float* __restrict__ bias0, const float* __restrict__ bias1, const float* __restrict__ bias2,
         const float* __restrict__ res, const float* __restrict__ rowscale,
         float* __restrict__ Cf, __nv_bfloat16* __restrict__ Cb,
         int M, int N, int Nb, int K,
         const int* __restrict__ gather, const int* __restrict__ gcount,
         int relu_flag) {
    constexpr int KC = (EB == 4) ? 16 : 32;   // k elems per chunk
    __shared__ __align__(16) char smA[2][128 * RB];
    __shared__ __align__(16) uint32_t smB[2][16 * 136];

    int e  = blockIdx.z;
    int m0 = blockIdx.y * 128, n0 = blockIdx.x * 128;
    const float* Bsrc; const float* bias; int nb0;
    if (B1) {
        int part = n0 >> 10; nb0 = n0 & 1023;
        Bsrc = part == 0 ? B0 : (part == 1 ? B1 : B2);
        bias = part == 0 ? bias0 : (part == 1 ? bias1 : bias2);
    } else { Bsrc = B0; bias = bias0; nb0 = n0; }
    const int* glist = nullptr; int mcnt = M;
    if (gather) {
        glist = gather + (size_t)e * T_;
        mcnt  = gcount[e];
        if (m0 >= mcnt) return;
        Bsrc += (size_t)e * K * Nb;
        bias += (size_t)e * Nb;
    }
    int tid = threadIdx.x;
    int wid = tid >> 5, lane = tid & 31;

    // A staging: thread -> rows (srow, srow+64), 16B col chunk c4
    int srow = tid >> 2, c4 = tid & 3;
    int rows[2] = { srow, srow + 64 };
    const char* aptr[2]; bool aval[2];
    #pragma unroll
    for (int u = 0; u < 2; u++) {
        int rr = m0 + rows[u]; int tok = rr; aval[u] = true;
        if (gather) { if (rr < mcnt) tok = glist[rr]; else { aval[u] = false; tok = 0; } }
        aptr[u] = A + (size_t)tok * K * EB + c4 * 16;
    }
    // B staging: warp w -> k-rows (wid, wid+8), cols lane*4
    const float* bbase = Bsrc + nb0 + lane * 4;

    int wm = wid & 3, wn = wid >> 2;
    int wr = wm * 32, wc = wn * 64;
    int gid = lane >> 2, tig = lane & 3;

    float acc[2][8][4];
    #pragma unroll
    for (int mt = 0; mt < 2; mt++)
        #pragma unroll
        for (int nt = 0; nt < 8; nt++)
            #pragma unroll
            for (int j = 0; j < 4; j++) acc[mt][nt][j] = 0.f;

    int nch = K / KC;

    // ---- staging helpers inlined via lambdas ----
    uint4 ra[2]; float4 rb[4];
    auto loadA = [&](int i) {
        size_t kb = (size_t)i * 64;
        #pragma unroll
        for (int u = 0; u < 2; u++) {
            ra[u] = aval[u] ? *(const uint4*)(aptr[u] + kb) : make_uint4(0,0,0,0);
            if (EB == 4) {
                ra[u].x = f2tf32(__uint_as_float(ra[u].x)); ra[u].y = f2tf32(__uint_as_float(ra[u].y));
                ra[u].z = f2tf32(__uint_as_float(ra[u].z)); ra[u].w = f2tf32(__uint_as_float(ra[u].w));
            }
        }
    };
    auto loadB = [&](int i) {
        int k0 = i * KC;
        if (EB == 4) {
            rb[0] = *(const float4*)(bbase + (size_t)(k0 + wid) * Nb);
            rb[1] = *(const float4*)(bbase + (size_t)(k0 + wid + 8) * Nb);
        } else {
            rb[0] = *(const float4*)(bbase + (size_t)(k0 + 2*wid) * Nb);
            rb[1] = *(const float4*)(bbase + (size_t)(k0 + 2*wid + 1) * Nb);
            rb[2] = *(const float4*)(bbase + (size_t)(k0 + 2*(wid+8)) * Nb);
            rb[3] = *(const float4*)(bbase + (size_t)(k0 + 2*(wid+8) + 1) * Nb);
        }
    };
    auto storeAB = [&](int buf) {
        #pragma unroll
        for (int u = 0; u < 2; u++)
            *(uint4*)&smA[buf][rows[u] * RB + c4 * 16] = ra[u];
        if (EB == 4) {
            *(uint4*)&smB[buf][wid * 136 + lane * 4] =
                make_uint4(f2tf32(rb[0].x), f2tf32(rb[0].y), f2tf32(rb[0].z), f2tf32(rb[0].w));
            *(uint4*)&smB[buf][(wid + 8) * 136 + lane * 4] =
                make_uint4(f2tf32(rb[1].x), f2tf32(rb[1].y), f2tf32(rb[1].z), f2tf32(rb[1].w));
        } else {
            *(uint4*)&smB[buf][wid * 136 + lane * 4] =
                make_uint4(packbf(rb[0].x, rb[1].x), packbf(rb[0].y, rb[1].y),
                           packbf(rb[0].z, rb[1].z), packbf(rb[0].w, rb[1].w));
            *(uint4*)&smB[buf][(wid + 8) * 136 + lane * 4] =
                make_uint4(packbf(rb[2].x, rb[3].x), packbf(rb[2].y, rb[3].y),
                           packbf(rb[2].z, rb[3].z), packbf(rb[2].w, rb[3].w));
        }
    };

    loadA(0); loadB(0); storeAB(0);
    __syncthreads();

    for (int i = 0; i < nch; i++) {
        int buf = i & 1;
        bool more = (i + 1 < nch);
        if (more) { loadA(i + 1); loadB(i + 1); }
        const uint32_t* bb = smB[buf];
        #pragma unroll
        for (int ks = 0; ks < 2; ks++) {
            uint32_t afr[2][4];
            int kb0 = (EB == 2) ? (ks * 16 + tig * 2) * 2 : (ks * 8 + tig) * 4;
            #pragma unroll
            for (int mt = 0; mt < 2; mt++) {
                const char* ap = &smA[buf][(wr + mt * 16 + gid) * RB + kb0];
                afr[mt][0] = lds32(ap);
                afr[mt][1] = lds32(ap + 8 * RB);
                afr[mt][2] = lds32(ap + 16);
                afr[mt][3] = lds32(ap + 8 * RB + 16);
            }
            int krow = ks * 8 + tig;
            #pragma unroll
            for (int nt = 0; nt < 8; nt++) {
                uint32_t b0 = bb[krow * 136 + wc + nt * 8 + gid];
                uint32_t b1 = bb[(krow + 4) * 136 + wc + nt * 8 + gid];
                if (EB == 2) { mma_bf16(acc[0][nt], afr[0], b0, b1); mma_bf16(acc[1][nt], afr[1], b0, b1); }
                else         { mma_tf32(acc[0][nt], afr[0], b0, b1); mma_tf32(acc[1][nt], afr[1], b0, b1); }
            }
        }
        if (more) storeAB(buf ^ 1);
        __syncthreads();
    }

    // epilogue
    #pragma unroll
    for (int mt = 0; mt < 2; mt++) {
        #pragma unroll
        for (int half = 0; half < 2; half++) {
            int r = m0 + wr + mt * 16 + gid + half * 8;
            int tok = r; bool valid = true;
            if (gather) { if (r < mcnt) tok = glist[r]; else valid = false; }
            if (!valid) continue;
            float sc = rowscale ? rowscale[tok] : 1.f;
            size_t ob = (size_t)tok * N;
            #pragma unroll
            for (int nt = 0; nt < 8; nt++) {
                int c  = n0 + wc + nt * 8 + tig * 2;       // output col
                int cb = nb0 + wc + nt * 8 + tig * 2;      // bias col
                float v0 = acc[mt][nt][half * 2 + 0] + bias[cb];
                float v1 = acc[mt][nt][half * 2 + 1] + bias[cb + 1];
                if (relu_flag) { v0 = fmaxf(v0, 0.f); v1 = fmaxf(v1, 0.f); }
                v0 *= sc; v1 *= sc;
                if (res) { v0 += res[ob + c]; v1 += res[ob + c + 1]; }
                if (Cb) {
                    Cb[ob + c]     = __float2bfloat16(v0);
                    Cb[ob + c + 1] = __float2bfloat16(v1);
                } else {
                    Cf[ob + c]     = v0;
                    Cf[ob + c + 1] = v1;
                }
            }
        }
    }
}

// ---------------- flash attention via mma.sync tf32 ----------------
// CTA: 128 q-rows of one (b,h); 8 warps x 16 rows; key tiles of 64.
// V stored in natural [key][d] layout (stride 72 words, 72%32==8 ->
// conflict-free direct B-fragment loads; no transpose staging).
#define QS_  68
#define VS_  72
#define ATTN_SMEM ((128*QS_ + 64*QS_ + 64*VS_ + 128*QS_) * 4)
__global__ void __launch_bounds__(256)
attn_mma(const float* __restrict__ qkv, float* __restrict__ o) {
    extern __shared__ uint32_t sm[];
    uint32_t* qS = sm;                    // [128][QS_]
    uint32_t* kS = qS + 128 * QS_;        // [64][QS_]
    uint32_t* vS = kS + 64 * QS_;         // [64][VS_]
    uint32_t* pS = vS + 64 * VS_;         // [8 warps * 16][QS_]

    int bh = blockIdx.y;
    int b = bh % B_, h = bh / B_;
    int s0 = blockIdx.x * 128;
    int tid = threadIdx.x, lane = tid & 31, wid = tid >> 5;
    int gid = lane >> 2, tig = lane & 3;
    int wr = wid * 16;
    const float scale = 0.125f;

    // stage Q (tf32): 128 rows
    {
        int lr = tid >> 1, lc0 = (tid & 1) * 32;
        int t = (s0 + lr) * B_ + b;
        const float* qp = qkv + (size_t)t * 3072 + h * DK_ + lc0;
        #pragma unroll
        for (int j = 0; j < 8; j++) {
            float4 f = *(const float4*)(qp + j * 4);
            *(uint4*)&qS[lr * QS_ + lc0 + j * 4] =
                make_uint4(f2tf32(f.x), f2tf32(f.y), f2tf32(f.z), f2tf32(f.w));
        }
    }

    float oacc[8][4];
    #pragma unroll
    for (int dt = 0; dt < 8; dt++)
        #pragma unroll
        for (int j = 0; j < 4; j++) oacc[dt][j] = 0.f;
    float mrow0 = -INFINITY, mrow1 = -INFINITY, lrow0 = 0.f, lrow1 = 0.f;

    int kr = tid >> 2, kc0 = (tid & 3) * 16;
    for (int n0 = 0; n0 < S_; n0 += 64) {
        // stage K (tf32) and V (tf32, natural layout)
        {
            int t = (n0 + kr) * B_ + b;
            const float* kp = qkv + (size_t)t * 3072 + 1024 + h * DK_ + kc0;
            const float* vp = qkv + (size_t)t * 3072 + 2048 + h * DK_ + kc0;
            #pragma unroll
            for (int j = 0; j < 4; j++) {
                float4 f = *(const float4*)(kp + j * 4);
                *(uint4*)&kS[kr * QS_ + kc0 + j * 4] =
                    make_uint4(f2tf32(f.x), f2tf32(f.y), f2tf32(f.z), f2tf32(f.w));
                float4 g = *(const float4*)(vp + j * 4);
                *(uint4*)&vS[kr * VS_ + kc0 + j * 4] =
                    make_uint4(f2tf32(g.x), f2tf32(g.y), f2tf32(g.z), f2tf32(g.w));
            }
        }
        __syncthreads();

        // scores: 16x64 per warp
        float sc[8][4];
        #pragma unroll
        for (int nt = 0; nt < 8; nt++)
            #pragma unroll
            for (int j = 0; j < 4; j++) sc[nt][j] = 0.f;
        #pragma unroll
        for (int kk = 0; kk < 8; kk++) {
            uint32_t a[4];
            const uint32_t* ar = &qS[(wr + gid) * QS_ + kk * 8 + tig];
            a[0] = ar[0]; a[1] = ar[8 * QS_]; a[2] = ar[4]; a[3] = ar[8 * QS_ + 4];
            #pragma unroll
            for (int nt = 0; nt < 8; nt++) {
                const uint32_t* br = &kS[(nt * 8 + gid) * QS_ + kk * 8 + tig];
                mma_tf32(sc[nt], a, br[0], br[4]);
            }
        }

        // online softmax (rows r0=wr+gid, r1=r0+8)
        float mx0 = -INFINITY, mx1 = -INFINITY;
        #pragma unroll
        for (int nt = 0; nt < 8; nt++) {
            sc[nt][0] *= scale; sc[nt][1] *= scale; sc[nt][2] *= scale; sc[nt][3] *= scale;
            mx0 = fmaxf(mx0, fmaxf(sc[nt][0], sc[nt][1]));
            mx1 = fmaxf(mx1, fmaxf(sc[nt][2], sc[nt][3]));
        }
        mx0 = fmaxf(mx0, __shfl_xor_sync(0xffffffffu, mx0, 1));
        mx0 = fmaxf(mx0, __shfl_xor_sync(0xffffffffu, mx0, 2));
        mx1 = fmaxf(mx1, __shfl_xor_sync(0xffffffffu, mx1, 1));
        mx1 = fmaxf(mx1, __shfl_xor_sync(0xffffffffu, mx1, 2));
        float nm0 = fmaxf(mrow0, mx0), nm1 = fmaxf(mrow1, mx1);
        float al0 = __expf(mrow0 - nm0), al1 = __expf(mrow1 - nm1);
        float ps0 = 0.f, ps1 = 0.f;
        uint32_t* pw = pS + wid * 16 * QS_;
        #pragma unroll
        for (int nt = 0; nt < 8; nt++) {
            float p0 = __expf(sc[nt][0] - nm0);
            float p1 = __expf(sc[nt][1] - nm0);
            float p2 = __expf(sc[nt][2] - nm1);
            float p3 = __expf(sc[nt][3] - nm1);
            ps0 += p0 + p1; ps1 += p2 + p3;
            int c = nt * 8 + tig * 2;
            pw[gid * QS_ + c]           = f2tf32(p0);
            pw[gid * QS_ + c + 1]       = f2tf32(p1);
            pw[(gid + 8) * QS_ + c]     = f2tf32(p2);
            pw[(gid + 8) * QS_ + c + 1] = f2tf32(p3);
        }
        ps0 += __shfl_xor_sync(0xffffffffu, ps0, 1);
        ps0 += __shfl_xor_sync(0xffffffffu, ps0, 2);
        ps1 += __shfl_xor_sync(0xffffffffu, ps1, 1);
        ps1 += __shfl_xor_sync(0xffffffffu, ps1, 2);
        lrow0 = lrow0 * al0 + ps0; mrow0 = nm0;
        lrow1 = lrow1 * al1 + ps1; mrow1 = nm1;
        #pragma unroll
        for (int dt = 0; dt < 8; dt++) {
            oacc[dt][0] *= al0; oacc[dt][1] *= al0;
            oacc[dt][2] *= al1; oacc[dt][3] *= al1;
        }
        __syncwarp();

        // P @ V : A from own-warp pS, B direct from natural-layout vS
        #pragma unroll
        for (int kk = 0; kk < 8; kk++) {
            uint32_t a[4];
            const uint32_t* ar = &pw[gid * QS_ + kk * 8 + tig];
            a[0] = ar[0]; a[1] = ar[8 * QS_]; a[2] = ar[4]; a[3] = ar[8 * QS_ + 4];
            int krow = kk * 8 + tig;
            #pragma unroll
            for (int dt = 0; dt < 8; dt++) {
                uint32_t b0 = vS[krow * VS_ + dt * 8 + gid];
                uint32_t b1 = vS[(krow + 4) * VS_ + dt * 8 + gid];
                mma_tf32(oacc[dt], a, b0, b1);
            }
        }
        __syncthreads();
    }

    // write O
    float inv0 = 1.f / lrow0, inv1 = 1.f / lrow1;
    int r0 = s0 + wr + gid, r1 = r0 + 8;
    size_t o0 = (size_t)(r0 * B_ + b) * D_ + h * DK_;
    size_t o1 = (size_t)(r1 * B_ + b) * D_ + h * DK_;
    #pragma unroll
    for (int dt = 0; dt < 8; dt++) {
        int c = dt * 8 + tig * 2;
        o[o0 + c]     = oacc[dt][0] * inv0;
        o[o0 + c + 1] = oacc[dt][1] * inv0;
        o[o1 + c]     = oacc[dt][2] * inv1;
        o[o1 + c + 1] = oacc[dt][3] * inv1;
    }
}

// ---------------- gate / routing ----------------
__global__ void gate_kernel(const float* __restrict__ z,
                            const float* __restrict__ wg,
                            const float* __restrict__ bg) {
    int t = blockIdx.x;
    int tid = threadIdx.x;
    int w = tid >> 5, lane = tid & 31;
    __shared__ float lg[E_];
    const float* row = z + (size_t)t * D_;
    float s = 0.f;
    for (int i = lane; i < D_; i += 32) s += row[i] * wg[i * E_ + w];
    #pragma unroll
    for (int off = 16; off; off >>= 1) s += __shfl_down_sync(0xffffffffu, s, off);
    if (lane == 0) lg[w] = s + bg[w];
    __syncthreads();
    if (tid == 0) {
        float mx = lg[0]; int am = 0;
        #pragma unroll
        for (int e = 1; e < E_; e++) if (lg[e] > mx) { mx = lg[e]; am = e; }
        float pr[E_], sum = 0.f;
        #pragma unroll
        for (int e = 0; e < E_; e++) { pr[e] = expf(lg[e] - mx); sum += pr[e]; }
        float inv = 1.f / sum;
        #pragma unroll
        for (int e = 0; e < E_; e++) g_probs[t * E_ + e] = pr[e] * inv;
        g_pmax[t] = pr[am] * inv;
        int pos = atomicAdd(&g_ecount[am], 1);
        g_etok[am * T_ + pos] = t;
    }
}

// ---------------- route_prob_sum (deterministic) ----------------
__global__ void rps_kernel(float* __restrict__ dout, int out_size) {
    int e = blockIdx.x;
    __shared__ float red[256];
    float s = 0.f;
    for (int t = threadIdx.x; t < T_; t += 256) s += g_probs[t * E_ + e];
    red[threadIdx.x] = s; __syncthreads();
    for (int o = 128; o; o >>= 1) { if (threadIdx.x < o) red[threadIdx.x] += red[threadIdx.x+o]; __syncthreads(); }
    if (threadIdx.x == 0 && out_size >= OUT_TOTAL) dout[(size_t)T_ * D_ + E_ + e] = red[0];
}

// ---------------- tail outputs ----------------
__global__ void tail_kernel(float* __restrict__ dout, int out_size) {
    if (out_size < OUT_TOTAL) return;
    int i = blockIdx.x * blockDim.x + threadIdx.x;
    size_t base = (size_t)T_ * D_;
    if (i < E_) dout[base + i] = (float)g_ecount[i];
    if (i == 0) dout[base + 2 * E_] = 0.f;
    if (i < T_) dout[base + 2 * E_ + 1 + i] = g_pmax[i];
}

// ---------------- launch ----------------
extern "C" void kernel_launch(void* const* d_in, const int* in_sizes, int n_in,
                              void* d_out, int out_size) {
    const float* x      = (const float*)d_in[0];
    const float* ln1_g  = (const float*)d_in[1];
    const float* ln1_b  = (const float*)d_in[2];
    const float* ln2_g  = (const float*)d_in[3];
    const float* ln2_b  = (const float*)d_in[4];
    const float* wq     = (const float*)d_in[5];
    const float* bq     = (const float*)d_in[6];
    const float* wk     = (const float*)d_in[7];
    const float* bk     = (const float*)d_in[8];
    const float* wv     = (const float*)d_in[9];
    const float* bv     = (const float*)d_in[10];
    const float* wo     = (const float*)d_in[11];
    const float* bo     = (const float*)d_in[12];
    const float* w_gate = (const float*)d_in[13];
    const float* b_gate = (const float*)d_in[14];
    const float* w1     = (const float*)d_in[15];
    const float* b1     = (const float*)d_in[16];
    const float* w2     = (const float*)d_in[17];
    const float* b2     = (const float*)d_in[18];
    float* out = (float*)d_out;

    float *z1, *qkv, *o, *x2, *z2, *pmaxp;
    __nv_bfloat16 *z2b, *hb;
    int *etok, *ecount;
    cudaGetSymbolAddress((void**)&z1,  g_z1);
    cudaGetSymbolAddress((void**)&qkv, g_qkv);
    cudaGetSymbolAddress((void**)&o,   g_o);
    cudaGetSymbolAddress((void**)&x2,  g_x2);
    cudaGetSymbolAddress((void**)&z2,  g_z2);
    cudaGetSymbolAddress((void**)&z2b, g_z2b);
    cudaGetSymbolAddress((void**)&hb,  g_hb);
    cudaGetSymbolAddress((void**)&etok,   g_etok);
    cudaGetSymbolAddress((void**)&ecount, g_ecount);
    cudaGetSymbolAddress((void**)&pmaxp,  g_pmax);

    cudaFuncSetAttribute(attn_mma, cudaFuncAttributeMaxDynamicSharedMemorySize, ATTN_SMEM);

    init_kernel<<<1, 32>>>();

    // LN1
    ln_kernel<<<T_, 256>>>(x, ln1_g, ln1_b, z1, nullptr);

    // fused QKV projection (tf32, direct-B): [T,1024] @ {wq|wk|wv} -> [T,3072]
    mma_gemm<4><<<dim3(3072/128, T_/128, 1), 256>>>(
        (const char*)z1, wq, wk, wv, bq, bk, bv,
        nullptr, nullptr, qkv, nullptr, T_, 3072, D_, D_, nullptr, nullptr, 0);

    // attention (tf32 mma.sync flash, 128 q-rows/CTA)
    attn_mma<<<dim3(S_/128, B_*H_), 256, ATTN_SMEM>>>(qkv, o);

    // output projection + residual (tf32, direct-B)
    mma_gemm<4><<<dim3(D_/128, T_/128, 1), 256>>>(
        (const char*)o, wo, nullptr, nullptr, bo, nullptr, nullptr,
        x, nullptr, x2, nullptr, T_, D_, D_, D_, nullptr, nullptr, 0);

    // LN2 (fp32 for gate + bf16 for MoE)
    ln_kernel<<<T_, 256>>>(x2, ln2_g, ln2_b, z2, z2b);

    // gate + routing
    gate_kernel<<<T_, 256>>>(z2, w_gate, b_gate);

    // MoE FFN (grouped by expert, bf16, direct-B from fp32 weights)
    mma_gemm<2><<<dim3(F_/128, T_/128, E_), 256>>>(
        (const char*)z2b, w1, nullptr, nullptr, b1, nullptr, nullptr,
        nullptr, nullptr, nullptr, hb, T_, F_, F_, D_, etok, ecount, 1);
    mma_gemm<2><<<dim3(D_/128, T_/128, E_), 256>>>(
        (const char*)hb, w2, nullptr, nullptr, b2, nullptr, nullptr,
        x2, pmaxp, out, nullptr, T_, D_, D_, F_, etok, ecount, 0);

    // aux outputs
    rps_kernel<<<E_, 256>>>(out, out_size);
    tail_kernel<<<(T_ + 255) / 256, 256>>>(out, out_size);
}

// round 7
// speedup vs baseline: 7.2832x; 1.1012x over previous
#include <cuda_runtime.h>
#include <cuda_bf16.h>
#include <math.h>
#include <stdint.h>

// Problem dims
#define S_  2048
#define B_  2
#define D_  1024
#define H_  16
#define DK_ 64
#define E_  8
#define F_  4096
#define T_  (S_*B_)          // 4096 tokens
#define OUT_TOTAL (T_*D_ + E_ + E_ + 1 + T_)

// ---------------- scratch (device globals) ----------------
__device__ float g_z1[T_*D_];
__device__ float g_qkv[(size_t)T_*3072];
__device__ float g_o [T_*D_];
__device__ float g_x2[T_*D_];
__device__ float g_z2[T_*D_];
__device__ __nv_bfloat16 g_z2b[T_*D_];
__device__ __nv_bfloat16 g_hb[(size_t)T_*F_];
__device__ float g_probs[T_*E_];
__device__ float g_pmax[T_];
__device__ int   g_etok[E_*T_];
__device__ int   g_ecount[E_];

__device__ __forceinline__ uint32_t f2tf32(float f) {
    uint32_t r; asm("cvt.rna.tf32.f32 %0, %1;" : "=r"(r) : "f"(f)); return r;
}
__device__ __forceinline__ uint32_t packbf(float lo, float hi) {
    __nv_bfloat162 t = __floats2bfloat162_rn(lo, hi);
    return *(uint32_t*)&t;
}
__device__ __forceinline__ void mma_bf16(float* c, const uint32_t* a, uint32_t b0, uint32_t b1) {
    asm volatile("mma.sync.aligned.m16n8k16.row.col.f32.bf16.bf16.f32 "
        "{%0,%1,%2,%3}, {%4,%5,%6,%7}, {%8,%9}, {%0,%1,%2,%3};"
        : "+f"(c[0]), "+f"(c[1]), "+f"(c[2]), "+f"(c[3])
        : "r"(a[0]), "r"(a[1]), "r"(a[2]), "r"(a[3]), "r"(b0), "r"(b1));
}
__device__ __forceinline__ void mma_tf32(float* c, const uint32_t* a, uint32_t b0, uint32_t b1) {
    asm volatile("mma.sync.aligned.m16n8k8.row.col.f32.tf32.tf32.f32 "
        "{%0,%1,%2,%3}, {%4,%5,%6,%7}, {%8,%9}, {%0,%1,%2,%3};"
        : "+f"(c[0]), "+f"(c[1]), "+f"(c[2]), "+f"(c[3])
        : "r"(a[0]), "r"(a[1]), "r"(a[2]), "r"(a[3]), "r"(b0), "r"(b1));
}
__device__ __forceinline__ uint32_t lds32(const char* p) {
    return *(const uint32_t*)p;
}
__device__ __forceinline__ uint32_t smem_u32(const void* p) {
    uint32_t a;
    asm("{ .reg .u64 t; cvta.to.shared.u64 t, %1; cvt.u32.u64 %0, t; }" : "=r"(a) : "l"(p));
    return a;
}
__device__ __forceinline__ void cpa16(uint32_t dst, const void* src) {
    asm volatile("cp.async.cg.shared.global [%0], [%1], 16;" :: "r"(dst), "l"(src));
}
#define CP_COMMIT() asm volatile("cp.async.commit_group;" ::: "memory")
#define CP_WAIT0()  asm volatile("cp.async.wait_group 0;" ::: "memory")

// ---------------- init ----------------
__global__ void init_kernel() {
    int i = threadIdx.x;
    if (i < E_) g_ecount[i] = 0;
}

// ---------------- LayerNorm (fp32 out + optional bf16 out) ----------------
__global__ void ln_kernel(const float* __restrict__ x,
                          const float* __restrict__ gam,
                          const float* __restrict__ bet,
                          float* __restrict__ z,
                          __nv_bfloat16* __restrict__ zb) {
    int t = blockIdx.x;
    const float* row = x + (size_t)t * D_;
    __shared__ float red[256];
    __shared__ float stats[2];
    float s = 0.f, sq = 0.f;
    for (int i = threadIdx.x; i < D_; i += 256) {
        float v = row[i]; s += v; sq += v * v;
    }
    red[threadIdx.x] = s; __syncthreads();
    for (int o = 128; o; o >>= 1) { if (threadIdx.x < o) red[threadIdx.x] += red[threadIdx.x+o]; __syncthreads(); }
    if (threadIdx.x == 0) stats[0] = red[0];
    __syncthreads();
    red[threadIdx.x] = sq; __syncthreads();
    for (int o = 128; o; o >>= 1) { if (threadIdx.x < o) red[threadIdx.x] += red[threadIdx.x+o]; __syncthreads(); }
    if (threadIdx.x == 0) stats[1] = red[0];
    __syncthreads();
    float mean = stats[0] * (1.f / D_);
    float var  = stats[1] * (1.f / D_) - mean * mean;
    float inv  = rsqrtf(var + 1e-5f);
    for (int i = threadIdx.x; i < D_; i += 256) {
        float v = (row[i] - mean) * inv * gam[i] + bet[i];
        z[(size_t)t * D_ + i] = v;
        if (zb) zb[(size_t)t * D_ + i] = __float2bfloat16(v);
    }
}

// ---------------- mma.sync GEMM with direct row-major B ----------------
// EB=4: tf32 via cp.async double-buffer (no gather). EB=2: bf16 register staging
// (gather/pack). smB row stride 136 words -> conflict-free B fragments.
#define RB 80   // smem A row bytes
template<int EB>
__global__ void __launch_bounds__(256)
mma_gemm(const char* __restrict__ A,
         const float* __restrict__ B0, const float* __restrict__ B1, const float* __restrict__ B2,
         const float* __restrict__ bias0, const float* __restrict__ bias1, const float* __restrict__ bias2,
         const float* __restrict__ res, const float* __restrict__ rowscale,
         float* __restrict__ Cf, __nv_bfloat16* __restrict__ Cb,
         int M, int N, int Nb, int K,
         const int* __restrict__ gather, const int* __restrict__ gcount,
         int relu_flag) {
    constexpr int KC = (EB == 4) ? 16 : 32;   // k elems per chunk
    __shared__ __align__(16) char smA[2][128 * RB];
    __shared__ __align__(16) uint32_t smB[2][16 * 136];

    int e  = blockIdx.z;
    int m0 = blockIdx.y * 128, n0 = blockIdx.x * 128;
    const float* Bsrc; const float* bias; int nb0;
    if (B1) {
        int part = n0 >> 10; nb0 = n0 & 1023;
        Bsrc = part == 0 ? B0 : (part == 1 ? B1 : B2);
        bias = part == 0 ? bias0 : (part == 1 ? bias1 : bias2);
    } else { Bsrc = B0; bias = bias0; nb0 = n0; }
    const int* glist = nullptr; int mcnt = M;
    if (gather) {
        glist = gather + (size_t)e * T_;
        mcnt  = gcount[e];
        if (m0 >= mcnt) return;
        Bsrc += (size_t)e * K * Nb;
        bias += (size_t)e * Nb;
    }
    int tid = threadIdx.x;
    int wid = tid >> 5, lane = tid & 31;

    int srow = tid >> 2, c4 = tid & 3;
    int rows[2] = { srow, srow + 64 };
    const char* aptr[2]; bool aval[2];
    #pragma unroll
    for (int u = 0; u < 2; u++) {
        int rr = m0 + rows[u]; int tok = rr; aval[u] = true;
        if (gather) { if (rr < mcnt) tok = glist[rr]; else { aval[u] = false; tok = 0; } }
        aptr[u] = A + (size_t)tok * K * EB + c4 * 16;
    }
    const float* bbase = Bsrc + nb0 + lane * 4;

    int wm = wid & 3, wn = wid >> 2;
    int wr = wm * 32, wc = wn * 64;
    int gid = lane >> 2, tig = lane & 3;

    float acc[2][8][4];
    #pragma unroll
    for (int mt = 0; mt < 2; mt++)
        #pragma unroll
        for (int nt = 0; nt < 8; nt++)
            #pragma unroll
            for (int j = 0; j < 4; j++) acc[mt][nt][j] = 0.f;

    int nch = K / KC;

    if (EB == 4) {
        // ---------- cp.async pipeline ----------
        uint32_t sA[2], sB[2];
        sA[0] = smem_u32(&smA[0][0]); sA[1] = smem_u32(&smA[1][0]);
        sB[0] = smem_u32(&smB[0][0]); sB[1] = smem_u32(&smB[1][0]);
        auto prefetch = [&](int i) {
            int buf = i & 1;
            size_t kb = (size_t)i * 64;
            cpa16(sA[buf] + rows[0] * RB + c4 * 16, aptr[0] + kb);
            cpa16(sA[buf] + rows[1] * RB + c4 * 16, aptr[1] + kb);
            int k0 = i * KC;
            cpa16(sB[buf] + (wid * 136 + lane * 4) * 4,       bbase + (size_t)(k0 + wid) * Nb);
            cpa16(sB[buf] + ((wid + 8) * 136 + lane * 4) * 4, bbase + (size_t)(k0 + wid + 8) * Nb);
            CP_COMMIT();
        };
        prefetch(0);
        CP_WAIT0(); __syncthreads();
        for (int i = 0; i < nch; i++) {
            int buf = i & 1;
            bool more = (i + 1 < nch);
            if (more) prefetch(i + 1);
            const uint32_t* bb = smB[buf];
            #pragma unroll
            for (int ks = 0; ks < 2; ks++) {
                uint32_t afr[2][4];
                int kb0 = (ks * 8 + tig) * 4;
                #pragma unroll
                for (int mt = 0; mt < 2; mt++) {
                    const char* ap = &smA[buf][(wr + mt * 16 + gid) * RB + kb0];
                    afr[mt][0] = lds32(ap);
                    afr[mt][1] = lds32(ap + 8 * RB);
                    afr[mt][2] = lds32(ap + 16);
                    afr[mt][3] = lds32(ap + 8 * RB + 16);
                }
                int krow = ks * 8 + tig;
                #pragma unroll
                for (int nt = 0; nt < 8; nt++) {
                    uint32_t b0 = bb[krow * 136 + wc + nt * 8 + gid];
                    uint32_t b1 = bb[(krow + 4) * 136 + wc + nt * 8 + gid];
                    mma_tf32(acc[0][nt], afr[0], b0, b1);
                    mma_tf32(acc[1][nt], afr[1], b0, b1);
                }
            }
            if (more) { CP_WAIT0(); __syncthreads(); }
        }
    } else {
        // ---------- register-staged bf16 path ----------
        uint4 ra[2]; float4 rb[4];
        auto loadA = [&](int i) {
            size_t kb = (size_t)i * 64;
            #pragma unroll
            for (int u = 0; u < 2; u++)
                ra[u] = aval[u] ? *(const uint4*)(aptr[u] + kb) : make_uint4(0,0,0,0);
        };
        auto loadB = [&](int i) {
            int k0 = i * KC;
            rb[0] = *(const float4*)(bbase + (size_t)(k0 + 2*wid) * Nb);
            rb[1] = *(const float4*)(bbase + (size_t)(k0 + 2*wid + 1) * Nb);
            rb[2] = *(const float4*)(bbase + (size_t)(k0 + 2*(wid+8)) * Nb);
            rb[3] = *(const float4*)(bbase + (size_t)(k0 + 2*(wid+8) + 1) * Nb);
        };
        auto storeAB = [&](int buf) {
            #pragma unroll
            for (int u = 0; u < 2; u++)
                *(uint4*)&smA[buf][rows[u] * RB + c4 * 16] = ra[u];
            *(uint4*)&smB[buf][wid * 136 + lane * 4] =
                make_uint4(packbf(rb[0].x, rb[1].x), packbf(rb[0].y, rb[1].y),
                           packbf(rb[0].z, rb[1].z), packbf(rb[0].w, rb[1].w));
            *(uint4*)&smB[buf][(wid + 8) * 136 + lane * 4] =
                make_uint4(packbf(rb[2].x, rb[3].x), packbf(rb[2].y, rb[3].y),
                           packbf(rb[2].z, rb[3].z), packbf(rb[2].w, rb[3].w));
        };
        loadA(0); loadB(0); storeAB(0);
        __syncthreads();
        for (int i = 0; i < nch; i++) {
            int buf = i & 1;
            bool more = (i + 1 < nch);
            if (more) { loadA(i + 1); loadB(i + 1); }
            const uint32_t* bb = smB[buf];
            #pragma unroll
            for (int ks = 0; ks < 2; ks++) {
                uint32_t afr[2][4];
                int kb0 = (ks * 16 + tig * 2) * 2;
                #pragma unroll
                for (int mt = 0; mt < 2; mt++) {
                    const char* ap = &smA[buf][(wr + mt * 16 + gid) * RB + kb0];
                    afr[mt][0] = lds32(ap);
                    afr[mt][1] = lds32(ap + 8 * RB);
                    afr[mt][2] = lds32(ap + 16);
                    afr[mt][3] = lds32(ap + 8 * RB + 16);
                }
                int krow = ks * 8 + tig;
                #pragma unroll
                for (int nt = 0; nt < 8; nt++) {
                    uint32_t b0 = bb[krow * 136 + wc + nt * 8 + gid];
                    uint32_t b1 = bb[(krow + 4) * 136 + wc + nt * 8 + gid];
                    mma_bf16(acc[0][nt], afr[0], b0, b1);
                    mma_bf16(acc[1][nt], afr[1], b0, b1);
                }
            }
            if (more) storeAB(buf ^ 1);
            __syncthreads();
        }
    }

    // epilogue
    #pragma unroll
    for (int mt = 0; mt < 2; mt++) {
        #pragma unroll
        for (int half = 0; half < 2; half++) {
            int r = m0 + wr + mt * 16 + gid + half * 8;
            int tok = r; bool valid = true;
            if (gather) { if (r < mcnt) tok = glist[r]; else valid = false; }
            if (!valid) continue;
            float sc = rowscale ? rowscale[tok] : 1.f;
            size_t ob = (size_t)tok * N;
            #pragma unroll
            for (int nt = 0; nt < 8; nt++) {
                int c  = n0 + wc + nt * 8 + tig * 2;
                int cb = nb0 + wc + nt * 8 + tig * 2;
                float v0 = acc[mt][nt][half * 2 + 0] + bias[cb];
                float v1 = acc[mt][nt][half * 2 + 1] + bias[cb + 1];
                if (relu_flag) { v0 = fmaxf(v0, 0.f); v1 = fmaxf(v1, 0.f); }
                v0 *= sc; v1 *= sc;
                if (res) { v0 += res[ob + c]; v1 += res[ob + c + 1]; }
                if (Cb) {
                    Cb[ob + c]     = __float2bfloat16(v0);
                    Cb[ob + c + 1] = __float2bfloat16(v1);
                } else {
                    Cf[ob + c]     = v0;
                    Cf[ob + c + 1] = v1;
                }
            }
        }
    }
}

// ---------------- flash attention: tf32 mma + cp.async K/V pipeline ----------------
// CTA: 128 q-rows of one (b,h); 8 warps x 16 rows; key tiles of 64.
// Q fragments hoisted to registers (staged through pS region once).
// K/V double-buffered via cp.async (raw fp32 -> truncated tf32 in MMA).
#define QS_  68
#define VS_  72
#define ATTN_SMEM ((128*QS_ + 2*64*QS_ + 2*64*VS_) * 4)
__global__ void __launch_bounds__(256, 2)
attn_mma(const float* __restrict__ qkv, float* __restrict__ o) {
    extern __shared__ uint32_t sm[];
    uint32_t* pS = sm;                    // [128][QS_] (Q staging, then P)
    uint32_t* kS = pS + 128 * QS_;        // [2][64][QS_]
    uint32_t* vS = kS + 2 * 64 * QS_;     // [2][64][VS_]

    int bh = blockIdx.y;
    int b = bh % B_, h = bh / B_;
    int s0 = blockIdx.x * 128;
    int tid = threadIdx.x, lane = tid & 31, wid = tid >> 5;
    int gid = lane >> 2, tig = lane & 3;
    int wr = wid * 16;
    const float scale = 0.125f;

    uint32_t pS_a = smem_u32(pS), kS_a = smem_u32(kS), vS_a = smem_u32(vS);

    // prologue: cp.async Q (128 rows) + K/V tile 0
    {
        int qr = tid >> 1, qseg = tid & 1;             // 2 threads/row, 8 segs each
        const float* qp = qkv + (size_t)((s0 + qr) * B_ + b) * 3072 + h * DK_ + qseg * 32;
        #pragma unroll
        for (int j = 0; j < 8; j++)
            cpa16(pS_a + (qr * QS_ + qseg * 32 + j * 4) * 4, qp + j * 4);
    }
    int kr = tid >> 2, kseg = tid & 3;                 // 4 threads/row, 4 segs each
    auto prefetchKV = [&](int i) {
        int buf = i & 1;
        const float* base = qkv + (size_t)((i * 64 + kr) * B_ + b) * 3072 + h * DK_ + kseg * 16;
        #pragma unroll
        for (int j = 0; j < 4; j++) {
            cpa16(kS_a + ((buf * 64 + kr) * QS_ + kseg * 16 + j * 4) * 4, base + 1024 + j * 4);
            cpa16(vS_a + ((buf * 64 + kr) * VS_ + kseg * 16 + j * 4) * 4, base + 2048 + j * 4);
        }
        CP_COMMIT();
    };
    prefetchKV(0);
    CP_WAIT0(); __syncthreads();

    // extract Q fragments (rna tf32) — own warp's rows only
    uint32_t qf[8][4];
    #pragma unroll
    for (int kk = 0; kk < 8; kk++) {
        const uint32_t* ar = &pS[(wr + gid) * QS_ + kk * 8 + tig];
        qf[kk][0] = f2tf32(__uint_as_float(ar[0]));
        qf[kk][1] = f2tf32(__uint_as_float(ar[8 * QS_]));
        qf[kk][2] = f2tf32(__uint_as_float(ar[4]));
        qf[kk][3] = f2tf32(__uint_as_float(ar[8 * QS_ + 4]));
    }

    float oacc[8][4];
    #pragma unroll
    for (int dt = 0; dt < 8; dt++)
        #pragma unroll
        for (int j = 0; j < 4; j++) oacc[dt][j] = 0.f;
    float mrow0 = -INFINITY, mrow1 = -INFINITY, lrow0 = 0.f, lrow1 = 0.f;
    uint32_t* pw = pS + wid * 16 * QS_;

    const int NT = S_ / 64;
    for (int i = 0; i < NT; i++) {
        int buf = i & 1;
        bool more = (i + 1 < NT);
        if (more) prefetchKV(i + 1);
        const uint32_t* kb = kS + buf * 64 * QS_;
        const uint32_t* vb = vS + buf * 64 * VS_;

        // scores 16x64
        float sc[8][4];
        #pragma unroll
        for (int nt = 0; nt < 8; nt++)
            #pragma unroll
            for (int j = 0; j < 4; j++) sc[nt][j] = 0.f;
        #pragma unroll
        for (int kk = 0; kk < 8; kk++) {
            #pragma unroll
            for (int nt = 0; nt < 8; nt++) {
                const uint32_t* br = &kb[(nt * 8 + gid) * QS_ + kk * 8 + tig];
                mma_tf32(sc[nt], qf[kk], br[0], br[4]);
            }
        }

        // online softmax
        float mx0 = -INFINITY, mx1 = -INFINITY;
        #pragma unroll
        for (int nt = 0; nt < 8; nt++) {
            sc[nt][0] *= scale; sc[nt][1] *= scale; sc[nt][2] *= scale; sc[nt][3] *= scale;
            mx0 = fmaxf(mx0, fmaxf(sc[nt][0], sc[nt][1]));
            mx1 = fmaxf(mx1, fmaxf(sc[nt][2], sc[nt][3]));
        }
        mx0 = fmaxf(mx0, __shfl_xor_sync(0xffffffffu, mx0, 1));
        mx0 = fmaxf(mx0, __shfl_xor_sync(0xffffffffu, mx0, 2));
        mx1 = fmaxf(mx1, __shfl_xor_sync(0xffffffffu, mx1, 1));
        mx1 = fmaxf(mx1, __shfl_xor_sync(0xffffffffu, mx1, 2));
        float nm0 = fmaxf(mrow0, mx0), nm1 = fmaxf(mrow1, mx1);
        float al0 = __expf(mrow0 - nm0), al1 = __expf(mrow1 - nm1);
        float ps0 = 0.f, ps1 = 0.f;
        #pragma unroll
        for (int nt = 0; nt < 8; nt++) {
            float p0 = __expf(sc[nt][0] - nm0);
            float p1 = __expf(sc[nt][1] - nm0);
            float p2 = __expf(sc[nt][2] - nm1);
            float p3 = __expf(sc[nt][3] - nm1);
            ps0 += p0 + p1; ps1 += p2 + p3;
            int c = nt * 8 + tig * 2;
            *(uint2*)&pw[gid * QS_ + c]       = make_uint2(f2tf32(p0), f2tf32(p1));
            *(uint2*)&pw[(gid + 8) * QS_ + c] = make_uint2(f2tf32(p2), f2tf32(p3));
        }
        ps0 += __shfl_xor_sync(0xffffffffu, ps0, 1);
        ps0 += __shfl_xor_sync(0xffffffffu, ps0, 2);
        ps1 += __shfl_xor_sync(0xffffffffu, ps1, 1);
        ps1 += __shfl_xor_sync(0xffffffffu, ps1, 2);
        lrow0 = lrow0 * al0 + ps0; mrow0 = nm0;
        lrow1 = lrow1 * al1 + ps1; mrow1 = nm1;
        #pragma unroll
        for (int dt = 0; dt < 8; dt++) {
            oacc[dt][0] *= al0; oacc[dt][1] *= al0;
            oacc[dt][2] *= al1; oacc[dt][3] *= al1;
        }
        __syncwarp();

        // P @ V
        #pragma unroll
        for (int kk = 0; kk < 8; kk++) {
            uint32_t a[4];
            const uint32_t* ar = &pw[gid * QS_ + kk * 8 + tig];
            a[0] = ar[0]; a[1] = ar[8 * QS_]; a[2] = ar[4]; a[3] = ar[8 * QS_ + 4];
            int krow = kk * 8 + tig;
            #pragma unroll
            for (int dt = 0; dt < 8; dt++) {
                uint32_t b0 = vb[krow * VS_ + dt * 8 + gid];
                uint32_t b1 = vb[(krow + 4) * VS_ + dt * 8 + gid];
                mma_tf32(oacc[dt], a, b0, b1);
            }
        }
        if (more) { CP_WAIT0(); __syncthreads(); }
    }

    // write O
    float inv0 = 1.f / lrow0, inv1 = 1.f / lrow1;
    int r0 = s0 + wr + gid, r1 = r0 + 8;
    size_t o0 = (size_t)(r0 * B_ + b) * D_ + h * DK_;
    size_t o1 = (size_t)(r1 * B_ + b) * D_ + h * DK_;
    #pragma unroll
    for (int dt = 0; dt < 8; dt++) {
        int c = dt * 8 + tig * 2;
        o[o0 + c]     = oacc[dt][0] * inv0;
        o[o0 + c + 1] = oacc[dt][1] * inv0;
        o[o1 + c]     = oacc[dt][2] * inv1;
        o[o1 + c + 1] = oacc[dt][3] * inv1;
    }
}

// ---------------- gate / routing ----------------
__global__ void gate_kernel(const float* __restrict__ z,
                            const float* __restrict__ wg,
                            const float* __restrict__ bg) {
    int t = blockIdx.x;
    int tid = threadIdx.x;
    int w = tid >> 5, lane = tid & 31;
    __shared__ float lg[E_];
    const float* row = z + (size_t)t * D_;
    float s = 0.f;
    for (int i = lane; i < D_; i += 32) s += row[i] * wg[i * E_ + w];
    #pragma unroll
    for (int off = 16; off; off >>= 1) s += __shfl_down_sync(0xffffffffu, s, off);
    if (lane == 0) lg[w] = s + bg[w];
    __syncthreads();
    if (tid == 0) {
        float mx = lg[0]; int am = 0;
        #pragma unroll
        for (int e = 1; e < E_; e++) if (lg[e] > mx) { mx = lg[e]; am = e; }
        float pr[E_], sum = 0.f;
        #pragma unroll
        for (int e = 0; e < E_; e++) { pr[e] = expf(lg[e] - mx); sum += pr[e]; }
        float inv = 1.f / sum;
        #pragma unroll
        for (int e = 0; e < E_; e++) g_probs[t * E_ + e] = pr[e] * inv;
        g_pmax[t] = pr[am] * inv;
        int pos = atomicAdd(&g_ecount[am], 1);
        g_etok[am * T_ + pos] = t;
    }
}

// ---------------- route_prob_sum (deterministic) ----------------
__global__ void rps_kernel(float* __restrict__ dout, int out_size) {
    int e = blockIdx.x;
    __shared__ float red[256];
    float s = 0.f;
    for (int t = threadIdx.x; t < T_; t += 256) s += g_probs[t * E_ + e];
    red[threadIdx.x] = s; __syncthreads();
    for (int o = 128; o; o >>= 1) { if (threadIdx.x < o) red[threadIdx.x] += red[threadIdx.x+o]; __syncthreads(); }
    if (threadIdx.x == 0 && out_size >= OUT_TOTAL) dout[(size_t)T_ * D_ + E_ + e] = red[0];
}

// ---------------- tail outputs ----------------
__global__ void tail_kernel(float* __restrict__ dout, int out_size) {
    if (out_size < OUT_TOTAL) return;
    int i = blockIdx.x * blockDim.x + threadIdx.x;
    size_t base = (size_t)T_ * D_;
    if (i < E_) dout[base + i] = (float)g_ecount[i];
    if (i == 0) dout[base + 2 * E_] = 0.f;
    if (i < T_) dout[base + 2 * E_ + 1 + i] = g_pmax[i];
}

// ---------------- launch ----------------
extern "C" void kernel_launch(void* const* d_in, const int* in_sizes, int n_in,
                              void* d_out, int out_size) {
    const float* x      = (const float*)d_in[0];
    const float* ln1_g  = (const float*)d_in[1];
    const float* ln1_b  = (const float*)d_in[2];
    const float* ln2_g  = (const float*)d_in[3];
    const float* ln2_b  = (const float*)d_in[4];
    const float* wq     = (const float*)d_in[5];
    const float* bq     = (const float*)d_in[6];
    const float* wk     = (const float*)d_in[7];
    const float* bk     = (const float*)d_in[8];
    const float* wv     = (const float*)d_in[9];
    const float* bv     = (const float*)d_in[10];
    const float* wo     = (const float*)d_in[11];
    const float* bo     = (const float*)d_in[12];
    const float* w_gate = (const float*)d_in[13];
    const float* b_gate = (const float*)d_in[14];
    const float* w1     = (const float*)d_in[15];
    const float* b1     = (const float*)d_in[16];
    const float* w2     = (const float*)d_in[17];
    const float* b2     = (const float*)d_in[18];
    float* out = (float*)d_out;

    float *z1, *qkv, *o, *x2, *z2, *pmaxp;
    __nv_bfloat16 *z2b, *hb;
    int *etok, *ecount;
    cudaGetSymbolAddress((void**)&z1,  g_z1);
    cudaGetSymbolAddress((void**)&qkv, g_qkv);
    cudaGetSymbolAddress((void**)&o,   g_o);
    cudaGetSymbolAddress((void**)&x2,  g_x2);
    cudaGetSymbolAddress((void**)&z2,  g_z2);
    cudaGetSymbolAddress((void**)&z2b, g_z2b);
    cudaGetSymbolAddress((void**)&hb,  g_hb);
    cudaGetSymbolAddress((void**)&etok,   g_etok);
    cudaGetSymbolAddress((void**)&ecount, g_ecount);
    cudaGetSymbolAddress((void**)&pmaxp,  g_pmax);

    cudaFuncSetAttribute(attn_mma, cudaFuncAttributeMaxDynamicSharedMemorySize, ATTN_SMEM);

    init_kernel<<<1, 32>>>();

    // LN1
    ln_kernel<<<T_, 256>>>(x, ln1_g, ln1_b, z1, nullptr);

    // fused QKV projection (tf32 cp.async)
    mma_gemm<4><<<dim3(3072/128, T_/128, 1), 256>>>(
        (const char*)z1, wq, wk, wv, bq, bk, bv,
        nullptr, nullptr, qkv, nullptr, T_, 3072, D_, D_, nullptr, nullptr, 0);

    // attention
    attn_mma<<<dim3(S_/128, B_*H_), 256, ATTN_SMEM>>>(qkv, o);

    // output projection + residual (tf32 cp.async)
    mma_gemm<4><<<dim3(D_/128, T_/128, 1), 256>>>(
        (const char*)o, wo, nullptr, nullptr, bo, nullptr, nullptr,
        x, nullptr, x2, nullptr, T_, D_, D_, D_, nullptr, nullptr, 0);

    // LN2
    ln_kernel<<<T_, 256>>>(x2, ln2_g, ln2_b, z2, z2b);

    // gate + routing
    gate_kernel<<<T_, 256>>>(z2, w_gate, b_gate);

    // MoE FFN (grouped by expert, bf16)
    mma_gemm<2><<<dim3(F_/128, T_/128, E_), 256>>>(
        (const char*)z2b, w1, nullptr, nullptr, b1, nullptr, nullptr,
        nullptr, nullptr, nullptr, hb, T_, F_, F_, D_, etok, ecount, 1);
    mma_gemm<2><<<dim3(D_/128, T_/128, E_), 256>>>(
        (const char*)hb, w2, nullptr, nullptr, b2, nullptr, nullptr,
        x2, pmaxp, out, nullptr, T_, D_, D_, F_, etok, ecount, 0);

    // aux outputs
    rps_kernel<<<E_, 256>>>(out, out_size);
    tail_kernel<<<(T_ + 255) / 256, 256>>>(out, out_size);
}